// round 10
// baseline (speedup 1.0000x reference)
#include <cuda_runtime.h>
#include <cuda_bf16.h>
#include <cuda_fp16.h>
#include <math.h>
#include <cstdint>

#define M_TOTAL 81920
#define NGROUP  2048
#define NENT    14541
#define NRELS   237
#define NENT_P  14592
#define K_PAD   640
#define K_PAD2  128

// ---------------- scratch (device globals) ----------------------------------
// gate-interleaved fp16 tables, 512-wide rows (col 4u+g; cols 400..511 zero)
__device__ __align__(16) __half g_Pe[3][(size_t)NENT*512];
__device__ __align__(16) __half g_Pr[3][NRELS*512];
__device__ __align__(16) __half g_R1[3][(size_t)NENT*512];
__device__ float  g_bperm[3][512];
__device__ float  g_h1c1[3][NENT*200];
__device__ float  g_c2[(size_t)3*M_TOTAL*100];
__device__ float  g_out[(size_t)M_TOTAL*600];
__device__ __align__(16) __half g_hGf[(size_t)M_TOTAL*600];
__device__ float  g_op [(size_t)M_TOTAL*100];
// fp16 GEMM operands (pads stay zero)
__device__ __align__(16) __half g_Af[(size_t)M_TOTAL*K_PAD];
__device__ __align__(16) __half g_BTf[640*K_PAD];
__device__ __align__(16) __half g_h2f[(size_t)3*M_TOTAL*K_PAD2];
__device__ __align__(16) __half g_Wf[3][512*K_PAD2];      // permuted Whh
// bf16 hi/lo splits (weights permuted)
__device__ __align__(16) __nv_bfloat16 g_WTh[6][512*K_PAD2];
__device__ __align__(16) __nv_bfloat16 g_WTl[6][512*K_PAD2];
__device__ __align__(16) __nv_bfloat16 g_Eh[2][NENT_P*K_PAD2];
__device__ __align__(16) __nv_bfloat16 g_El[2][NENT_P*K_PAD2];
__device__ __align__(16) __nv_bfloat16 g_Rh[2][256*K_PAD2];
__device__ __align__(16) __nv_bfloat16 g_Rl[2][256*K_PAD2];
__device__ __align__(16) __nv_bfloat16 g_h1h[3][NENT_P*K_PAD2];
__device__ __align__(16) __nv_bfloat16 g_h1l[3][NENT_P*K_PAD2];

__device__ __forceinline__ float sigmoidf_(float x){
    return __fdividef(1.f, 1.f + __expf(-x));
}
__device__ __forceinline__ float tanhf_(float x){
    float xc = fminf(fmaxf(x,-15.f),15.f);
    float e = __expf(2.f*xc);
    return __fdividef(e-1.f, e+1.f);
}
__device__ __forceinline__ void split2(float v, __nv_bfloat16* ph, __nv_bfloat16* pl){
    __nv_bfloat16 h = __float2bfloat16(v);
    *ph = h;
    *pl = __float2bfloat16(v - __bfloat162float(h));
}
__device__ __forceinline__ void storeh4(float4 v, __half* p){
    ((__half2*)p)[0] = __floats2half2_rn(v.x, v.y);
    ((__half2*)p)[1] = __floats2half2_rn(v.z, v.w);
}

// ======================= MMA plumbing =======================================
__device__ __forceinline__ void cp16(unsigned saddr, const void* g){
    asm volatile("cp.async.cg.shared.global [%0], [%1], 16;" :: "r"(saddr), "l"(g));
}
__device__ __forceinline__ void cp_commit(){
    asm volatile("cp.async.commit_group;" ::: "memory");
}
template<int N> __device__ __forceinline__ void cp_wait(){
    asm volatile("cp.async.wait_group %0;" :: "n"(N) : "memory");
}
__device__ __forceinline__ void ldm4(uint32_t* r, unsigned addr){
    asm volatile("ldmatrix.sync.aligned.m8n8.x4.shared.b16 {%0,%1,%2,%3}, [%4];"
        : "=r"(r[0]), "=r"(r[1]), "=r"(r[2]), "=r"(r[3]) : "r"(addr));
}
__device__ __forceinline__ void mma16816(float* d, const uint32_t* a, uint32_t b0, uint32_t b1){
    asm volatile("mma.sync.aligned.m16n8k16.row.col.f32.bf16.bf16.f32 "
        "{%0,%1,%2,%3},{%4,%5,%6,%7},{%8,%9},{%0,%1,%2,%3};"
        : "+f"(d[0]), "+f"(d[1]), "+f"(d[2]), "+f"(d[3])
        : "r"(a[0]), "r"(a[1]), "r"(a[2]), "r"(a[3]), "r"(b0), "r"(b1));
}
__device__ __forceinline__ void mma16816h(float* d, const uint32_t* a, uint32_t b0, uint32_t b1){
    asm volatile("mma.sync.aligned.m16n8k16.row.col.f32.f16.f16.f32 "
        "{%0,%1,%2,%3},{%4,%5,%6,%7},{%8,%9},{%0,%1,%2,%3};"
        : "+f"(d[0]), "+f"(d[1]), "+f"(d[2]), "+f"(d[3])
        : "r"(a[0]), "r"(a[1]), "r"(a[2]), "r"(a[3]), "r"(b0), "r"(b1));
}

#define STG_F16 24576
#define MMF_SMEM (2*STG_F16)

__device__ __forceinline__ void stageF(unsigned sb,
    const __half* A, size_t lda, const __half* B, size_t ldb, int kcol, int tid)
{
    for (int i=tid;i<512;i+=256){
        int r=i>>3, c=i&7;
        unsigned off = (unsigned)((r*128 + c*16) ^ ((r&7)<<4));
        cp16(sb + off, A + (size_t)r*lda + kcol + c*8);
    }
    for (int i=tid;i<1024;i+=256){
        int r=i>>3, c=i&7;
        unsigned off = (unsigned)((r*128 + c*16) ^ ((r&7)<<4));
        cp16(sb + 8192 + off, B + (size_t)r*ldb + kcol + c*8);
    }
}

// ======================= fp16 GEMM for g_hGf ================================
__global__ void __launch_bounds__(256,3) mma_f16()
{
    extern __shared__ char smraw[];
    unsigned sbase;
    asm("{ .reg .u64 t; cvta.to.shared.u64 t, %1; cvt.u32.u64 %0, t; }" : "=r"(sbase) : "l"(smraw));
    int tid=threadIdx.x, wid=tid>>5, lane=tid&31;
    int wm = wid & 1, wn = wid >> 1;
    int ncol0 = blockIdx.x*128, mrow0 = blockIdx.y*64;

    const __half* A = g_Af + (size_t)mrow0*K_PAD;
    const __half* B = g_BTf + (size_t)ncol0*K_PAD;

    float acc[2][4][4];
    #pragma unroll
    for (int i=0;i<2;i++)
        #pragma unroll
        for (int j=0;j<4;j++)
            #pragma unroll
            for (int q=0;q<4;q++) acc[i][j][q]=0.f;

    stageF(sbase,           A,K_PAD,B,K_PAD, 0,  tid); cp_commit();
    stageF(sbase + STG_F16, A,K_PAD,B,K_PAD, 64, tid); cp_commit();

    int lr  = lane & 15;
    int lhb = (lane >> 4) << 4;

    for (int k=0;k<10;k++){
        if (k < 9) cp_wait<1>(); else cp_wait<0>();
        __syncthreads();
        unsigned st = sbase + (unsigned)(k&1)*STG_F16;
        unsigned sA = st, sB = st+8192;
        #pragma unroll
        for (int kk=0;kk<4;kk++){
            int cb = kk*32 + lhb;
            uint32_t ah[2][4], bb[2][4];
            #pragma unroll
            for (int mt=0;mt<2;mt++){
                int r = wm*32 + mt*16 + lr;
                unsigned off = (unsigned)((r*128 + cb) ^ ((r&7)<<4));
                ldm4(ah[mt], sA + off);
            }
            #pragma unroll
            for (int ng=0;ng<2;ng++){
                int n = wn*32 + ng*16 + lr;
                unsigned off = (unsigned)((n*128 + cb) ^ ((n&7)<<4));
                ldm4(bb[ng], sB + off);
            }
            #pragma unroll
            for (int mt=0;mt<2;mt++){
                #pragma unroll
                for (int nt=0;nt<4;nt++){
                    int ng = nt>>1, s = nt&1;
                    mma16816h(acc[mt][nt], ah[mt], bb[ng][s], bb[ng][s+2]);
                }
            }
        }
        __syncthreads();
        if (k+2 < 10){
            stageF(st, A,K_PAD,B,K_PAD, (k+2)*64, tid);
            cp_commit();
        }
    }
    #pragma unroll
    for (int mt=0;mt<2;mt++){
        int rbase = mrow0 + wm*32 + mt*16 + (lane>>2);
        #pragma unroll
        for (int nt=0;nt<4;nt++){
            int col = ncol0 + wn*32 + nt*8 + (lane&3)*2;
            if (col < 600){
                *(__half2*)(g_hGf + (size_t)rbase*600 + col)     = __floats2half2_rn(acc[mt][nt][0], acc[mt][nt][1]);
                *(__half2*)(g_hGf + (size_t)(rbase+8)*600 + col) = __floats2half2_rn(acc[mt][nt][2], acc[mt][nt][3]);
            }
        }
    }
}

// ======================= fused R2 GEMM + step3 cell =========================
__global__ void __launch_bounds__(256,3) mma_lstm3(const int* __restrict__ bh,
                                                   const int* __restrict__ bt)
{
    extern __shared__ char smraw[];
    unsigned sbase;
    asm("{ .reg .u64 t; cvta.to.shared.u64 t, %1; cvt.u32.u64 %0, t; }" : "=r"(sbase) : "l"(smraw));
    __shared__ int idxs[64];
    int tid=threadIdx.x, wid=tid>>5, lane=tid&31;
    int wm = wid & 1, wn = wid >> 1;
    int ncol0 = blockIdx.x*128, mrow0 = blockIdx.y*64;
    int l = blockIdx.z;
    int u0 = ncol0 >> 2;   // CTA base unit (0,32,64,96)

    if (tid < 64) idxs[tid] = (l==1)? bh[mrow0+tid] : bt[mrow0+tid];

    const __half* A = g_h2f + (size_t)l*M_TOTAL*K_PAD2 + (size_t)mrow0*K_PAD2;
    const __half* B = g_Wf[l] + (size_t)ncol0*K_PAD2;

    float acc[2][4][4];
    #pragma unroll
    for (int i=0;i<2;i++)
        #pragma unroll
        for (int j=0;j<4;j++)
            #pragma unroll
            for (int q=0;q<4;q++) acc[i][j][q]=0.f;

    stageF(sbase,           A,K_PAD2,B,K_PAD2, 0,  tid); cp_commit();
    stageF(sbase + STG_F16, A,K_PAD2,B,K_PAD2, 64, tid); cp_commit();

    int lr  = lane & 15;
    int lhb = (lane >> 4) << 4;

    for (int k=0;k<2;k++){
        if (k==0) cp_wait<1>(); else cp_wait<0>();
        __syncthreads();
        unsigned st = sbase + (unsigned)(k&1)*STG_F16;
        unsigned sA = st, sB = st+8192;
        #pragma unroll
        for (int kk=0;kk<4;kk++){
            int cb = kk*32 + lhb;
            uint32_t ah[2][4], bb[2][4];
            #pragma unroll
            for (int mt=0;mt<2;mt++){
                int r = wm*32 + mt*16 + lr;
                unsigned off = (unsigned)((r*128 + cb) ^ ((r&7)<<4));
                ldm4(ah[mt], sA + off);
            }
            #pragma unroll
            for (int ng=0;ng<2;ng++){
                int n = wn*32 + ng*16 + lr;
                unsigned off = (unsigned)((n*128 + cb) ^ ((n&7)<<4));
                ldm4(bb[ng], sB + off);
            }
            #pragma unroll
            for (int mt=0;mt<2;mt++){
                #pragma unroll
                for (int nt=0;nt<4;nt++){
                    int ng = nt>>1, s = nt&1;
                    mma16816h(acc[mt][nt], ah[mt], bb[ng][s], bb[ng][s+2]);
                }
            }
        }
        __syncthreads();
    }

    // ---- epilogue: stage c2 + Pe, apply cell, repack, write ----
    float*  c2s = (float*)smraw;                     // [64][33]
    __half* pes = (__half*)(smraw + 64*33*4);        // [64][136]
    float*  hs  = (float*)(smraw + 64*33*4 + 64*136*2); // [64][33]

    const float* C2 = g_c2 + (size_t)l*M_TOTAL*100;
    for (int i=tid;i<2048;i+=256){
        int r=i>>5, c=i&31; int u=u0+c;
        c2s[r*33+c] = (u<100)? C2[(size_t)(mrow0+r)*100 + u] : 0.f;
    }
    const __half* PeT = g_Pe[l];
    for (int i=tid;i<1024;i+=256){
        int r=i>>4, c=i&15;
        const __half* src = PeT + (size_t)idxs[r]*512 + 4*u0 + c*8;
        *(uint4*)&pes[r*136 + c*8] = *(const uint4*)src;
    }
    __syncthreads();

    int r01 = lane & 3;
    int rowq = lane >> 2;
    bool even = !(r01 & 1);
    #pragma unroll
    for (int mt=0;mt<2;mt++){
        #pragma unroll
        for (int nt=0;nt<4;nt++){
            float s0 = __shfl_xor_sync(0xffffffffu, acc[mt][nt][0], 1);
            float s1 = __shfl_xor_sync(0xffffffffu, acc[mt][nt][1], 1);
            float s2 = __shfl_xor_sync(0xffffffffu, acc[mt][nt][2], 1);
            float s3 = __shfl_xor_sync(0xffffffffu, acc[mt][nt][3], 1);
            int uu = wn*8 + nt*2 + (r01>>1);
            int rloc = wm*32 + mt*16 + rowq + (even? 0 : 8);
            float iv,fv,gv,ov;
            if (even){ iv=acc[mt][nt][0]; fv=acc[mt][nt][1]; gv=s0; ov=s1; }
            else     { iv=s2;             fv=s3;             gv=acc[mt][nt][2]; ov=acc[mt][nt][3]; }
            const __half2* pep = (const __half2*)&pes[rloc*136 + uu*4];
            float2 pif = __half22float2(pep[0]);
            float2 pgo = __half22float2(pep[1]);
            float4 bb4 = *(const float4*)&g_bperm[l][4*(u0+uu)];
            iv += pif.x + bb4.x; fv += pif.y + bb4.y;
            gv += pgo.x + bb4.z; ov += pgo.y + bb4.w;
            float c2 = c2s[rloc*33+uu];
            float c3 = sigmoidf_(fv)*c2 + sigmoidf_(iv)*tanhf_(gv);
            hs[rloc*33+uu] = sigmoidf_(ov)*tanhf_(c3);
        }
    }
    __syncthreads();

    int nvalid = 100 - u0; if (nvalid > 32) nvalid = 32;
    for (int rr=0;rr<8;rr++){
        int r = wid*8 + rr;
        size_t grow = (size_t)(mrow0 + r);
        if (lane < nvalid){
            float h = hs[r*33+lane];
            if (l==2){
                g_op[grow*100 + u0 + lane] = h;
            } else {
                int dst0 = (l==0)? 400 : 100;
                g_Af[grow*K_PAD + dst0 + u0 + lane] = __float2half(h);
                if ((grow % 80u)==0u)
                    g_out[grow*600 + dst0 + u0 + lane] = h;
            }
        }
    }
}

// ======================= bf16 3-term GEMM (vocab-level) =====================
#define STG_BYTES 49152
#define MM_SMEM   (2*STG_BYTES)

__device__ __forceinline__ void stageG(unsigned sb,
    const __nv_bfloat16* Ah, const __nv_bfloat16* Al, size_t lda, int mrow0, int Mv,
    const __nv_bfloat16* Bh, const __nv_bfloat16* Bl, size_t ldb, int ncol0,
    int kcol, int tid)
{
    for (int i=tid;i<512;i+=256){
        int r=i>>3, c=i&7;
        unsigned off = (unsigned)((r*128 + c*16) ^ ((r&7)<<4));
        int ra = mrow0 + r; if (ra >= Mv) ra = Mv-1;
        cp16(sb + off,         Ah + (size_t)ra*lda + kcol + c*8);
        cp16(sb + 8192 + off,  Al + (size_t)ra*lda + kcol + c*8);
    }
    for (int i=tid;i<1024;i+=256){
        int r=i>>3, c=i&7;
        unsigned off = (unsigned)((r*128 + c*16) ^ ((r&7)<<4));
        cp16(sb + 16384 + off,  Bh + (size_t)(ncol0+r)*ldb + kcol + c*8);
        cp16(sb + 32768 + off,  Bl + (size_t)(ncol0+r)*ldb + kcol + c*8);
    }
}

// which 2: Pe[z]  3: Pr[z]  4: R1[z]   (outputs fp16, 512-wide)
__global__ void __launch_bounds__(256,2) mma_gemm(int which)
{
    extern __shared__ char smraw[];
    unsigned sbase;
    asm("{ .reg .u64 t; cvta.to.shared.u64 t, %1; cvt.u32.u64 %0, t; }" : "=r"(sbase) : "l"(smraw));

    const __nv_bfloat16 *Ah,*Al,*Bh,*Bl; __half* C;
    int Mv;
    int z = blockIdx.z;
    switch (which){
      case 2: {
        int e = (z==2)? 1 : 0;
        Ah=g_Eh[e]; Al=g_El[e]; Bh=g_WTh[3+z]; Bl=g_WTl[3+z]; C=g_Pe[z]; Mv=NENT; break; }
      case 3: {
        int e = (z==2)? 1 : 0;
        Ah=g_Rh[e]; Al=g_Rl[e]; Bh=g_WTh[3+z]; Bl=g_WTl[3+z]; C=g_Pr[z]; Mv=NRELS; break; }
      default:
        Ah=g_h1h[z]; Al=g_h1l[z]; Bh=g_WTh[z]; Bl=g_WTl[z]; C=g_R1[z]; Mv=NENT; break;
    }
    const int ldc=512, nch=2;
    const size_t lda=K_PAD2, ldb=K_PAD2;

    int tid=threadIdx.x, wid=tid>>5, lane=tid&31;
    int wm = wid & 1, wn = wid >> 1;
    int ncol0 = blockIdx.x*128, mrow0 = blockIdx.y*64;

    float acc[2][4][4];
    #pragma unroll
    for (int i=0;i<2;i++)
        #pragma unroll
        for (int j=0;j<4;j++)
            #pragma unroll
            for (int q=0;q<4;q++) acc[i][j][q]=0.f;

    stageG(sbase,             Ah,Al,lda,mrow0,Mv, Bh,Bl,ldb,ncol0, 0,  tid); cp_commit();
    stageG(sbase + STG_BYTES, Ah,Al,lda,mrow0,Mv, Bh,Bl,ldb,ncol0, 64, tid); cp_commit();

    int lr  = lane & 15;
    int lhb = (lane >> 4) << 4;

    for (int k=0;k<nch;k++){
        if (k < nch-1) cp_wait<1>(); else cp_wait<0>();
        __syncthreads();
        unsigned st = sbase + (unsigned)(k&1)*STG_BYTES;
        unsigned sAh = st, sAl = st+8192, sBh = st+16384, sBl = st+32768;

        #pragma unroll
        for (int kk=0;kk<4;kk++){
            int cb = kk*32 + lhb;
            uint32_t ah[2][4], al[2][4], bh[2][4], bl[2][4];
            #pragma unroll
            for (int mt=0;mt<2;mt++){
                int r = wm*32 + mt*16 + lr;
                unsigned off = (unsigned)((r*128 + cb) ^ ((r&7)<<4));
                ldm4(ah[mt], sAh + off);
                ldm4(al[mt], sAl + off);
            }
            #pragma unroll
            for (int ng=0;ng<2;ng++){
                int n = wn*32 + ng*16 + lr;
                unsigned off = (unsigned)((n*128 + cb) ^ ((n&7)<<4));
                ldm4(bh[ng], sBh + off);
                ldm4(bl[ng], sBl + off);
            }
            #pragma unroll
            for (int mt=0;mt<2;mt++){
                #pragma unroll
                for (int nt=0;nt<4;nt++){
                    int ng = nt>>1, s = nt&1;
                    mma16816(acc[mt][nt], ah[mt], bh[ng][s], bh[ng][s+2]);
                    mma16816(acc[mt][nt], ah[mt], bl[ng][s], bl[ng][s+2]);
                    mma16816(acc[mt][nt], al[mt], bh[ng][s], bh[ng][s+2]);
                }
            }
        }
        __syncthreads();
        if (k+2 < nch){
            stageG(st, Ah,Al,lda,mrow0,Mv, Bh,Bl,ldb,ncol0, (k+2)*64, tid);
            cp_commit();
        }
    }

    #pragma unroll
    for (int mt=0;mt<2;mt++){
        int rbase = mrow0 + wm*32 + mt*16 + (lane>>2);
        #pragma unroll
        for (int nt=0;nt<4;nt++){
            int col = ncol0 + wn*32 + nt*8 + (lane&3)*2;
            if (rbase < Mv)
                *(__half2*)(C + (size_t)rbase*ldc + col)     = __floats2half2_rn(acc[mt][nt][0], acc[mt][nt][1]);
            if (rbase+8 < Mv)
                *(__half2*)(C + (size_t)(rbase+8)*ldc + col) = __floats2half2_rn(acc[mt][nt][2], acc[mt][nt][3]);
        }
    }
}

// ---------------------------------------------------------------------------
// conversions
// ---------------------------------------------------------------------------
__global__ void convB_kernel(const float* __restrict__ W1)
{
    int i = blockIdx.x*256 + threadIdx.x;
    if (i >= 600*600) return;
    int n = i / 600, k = i - n*600;
    g_BTf[(size_t)n*K_PAD + k] = __float2half(W1[(size_t)k*600 + n]);
}
__global__ void convW6_kernel(const float* __restrict__ Whf, const float* __restrict__ Whb,
                              const float* __restrict__ Whp, const float* __restrict__ Wif,
                              const float* __restrict__ Wib, const float* __restrict__ Wip)
{
    int i = blockIdx.x*256 + threadIdx.x;
    if (i >= 6*400*100) return;
    int m = i / 40000; int rem = i - m*40000;
    int n = rem/100, k = rem - n*100;
    const float* W;
    switch(m){ case 0:W=Whf;break; case 1:W=Whb;break; case 2:W=Whp;break;
               case 3:W=Wif;break; case 4:W=Wib;break; default:W=Wip;break; }
    float v = W[n*100+k];
    int p = 4*(n%100) + (n/100);     // gate-interleaved row
    split2(v, &g_WTh[m][p*K_PAD2 + k], &g_WTl[m][p*K_PAD2 + k]);
    if (m < 3) g_Wf[m][p*K_PAD2 + k] = __float2half(v);
}
__global__ void bias_perm_kernel(const float* __restrict__ b_f,
                                 const float* __restrict__ b_b,
                                 const float* __restrict__ b_p)
{
    int i = blockIdx.x*256 + threadIdx.x;
    if (i >= 3*400) return;
    int l = i/400, n = i - l*400;
    const float* b = (l==0)? b_f : (l==1)? b_b : b_p;
    g_bperm[l][4*(n%100) + (n/100)] = b[n];
}
__global__ void convE_kernel(const float* __restrict__ ent, const float* __restrict__ ent1,
                             const float* __restrict__ rel, const float* __restrict__ rel1)
{
    int i = blockIdx.x*256 + threadIdx.x;
    if (i < 2*NENT*100){
        int e = i / (NENT*100); int rem = i - e*(NENT*100);
        int r = rem/100, k = rem - r*100;
        const float* src = e ? ent1 : ent;
        split2(src[(size_t)r*100+k], &g_Eh[e][(size_t)r*K_PAD2+k], &g_El[e][(size_t)r*K_PAD2+k]);
    } else {
        int j = i - 2*NENT*100;
        if (j >= 2*NRELS*100) return;
        int e = j / (NRELS*100); int rem = j - e*(NRELS*100);
        int r = rem/100, k = rem - r*100;
        const float* src = e ? rel1 : rel;
        split2(src[(size_t)r*100+k], &g_Rh[e][(size_t)r*K_PAD2+k], &g_Rl[e][(size_t)r*K_PAD2+k]);
    }
}

// ---------------------------------------------------------------------------
__global__ void step1_kernel()
{
    int idx = blockIdx.x*256 + threadIdx.x;
    if (idx >= 3*NENT*100) return;
    int l   = idx / (NENT*100);
    int rem = idx - l*(NENT*100);
    int e = rem/100, j = rem - e*100;
    const __half* P = g_Pe[l] + (size_t)e*512 + 4*j;
    float2 pif = __half22float2(((const __half2*)P)[0]);
    float2 pgo = __half22float2(((const __half2*)P)[1]);
    float4 bb  = *(const float4*)&g_bperm[l][4*j];
    float iv = pif.x + bb.x;
    float gv = pgo.x + bb.z;
    float ov = pgo.y + bb.w;
    float c1 = sigmoidf_(iv) * tanhf_(gv);
    float h1 = sigmoidf_(ov) * tanhf_(c1);
    g_h1c1[l][(size_t)e*200 + j]       = h1;
    g_h1c1[l][(size_t)e*200 + 100 + j] = c1;
    split2(h1, &g_h1h[l][(size_t)e*K_PAD2 + j], &g_h1l[l][(size_t)e*K_PAD2 + j]);
}

// ---------------------------------------------------------------------------
__global__ void __launch_bounds__(256) step12_kernel(
    const int* __restrict__ bh, const int* __restrict__ br, const int* __restrict__ bt)
{
    __shared__ int ih[64], ir[64], it[64];
    int tid=threadIdx.x; int row0=blockIdx.x*64;
    if (tid<64)        ih[tid]     = bh[row0+tid];
    else if (tid<128)  ir[tid-64]  = br[row0+tid-64];
    else if (tid<192)  it[tid-128] = bt[row0+tid-128];
    __syncthreads();
    for (int l=0;l<3;l++){
        const __half* Pr = g_Pr[l];
        const __half* R1 = g_R1[l];
        const float*  HC = g_h1c1[l];
        const float*  BP = g_bperm[l];
        for (int t=tid;t<1600;t+=256){
            int row=t/25, q=t-row*25; int j=q*4;
            int fi = (l==1)? it[row] : ih[row];
            size_t grow=(size_t)(row0+row);
            bool emit_out = ((grow % 80u)==0u) && (l<2);
            float4 h1v = *(const float4*)&HC[(size_t)fi*200 + j];
            float4 c1v = *(const float4*)&HC[(size_t)fi*200 + 100 + j];
            if (l==0){
                if (emit_out) *(float4*)&g_out[grow*600 + j] = h1v;
                storeh4(h1v, &g_Af[grow*K_PAD + j]);
            } else if (l==1){
                if (emit_out) *(float4*)&g_out[grow*600 + 500 + j] = h1v;
                storeh4(h1v, &g_Af[grow*K_PAD + 500 + j]);
            }
            // contiguous gate loads: cols 4j..4j+15
            const __half* pr = Pr + (size_t)ir[row]*512 + 4*j;
            const __half* r1 = R1 + (size_t)fi*512 + 4*j;
            uint4 pa = *(const uint4*)pr, pb = *(const uint4*)(pr+8);
            uint4 ra = *(const uint4*)r1, rb = *(const uint4*)(r1+8);
            __half2 ph[8], rh[8];
            *(uint4*)&ph[0]=pa; *(uint4*)&ph[4]=pb;
            *(uint4*)&rh[0]=ra; *(uint4*)&rh[4]=rb;
            float c1a[4] = {c1v.x,c1v.y,c1v.z,c1v.w};
            float4 c2v, h2v;
            float* c2p = &c2v.x; float* h2p = &h2v.x;
            #pragma unroll
            for (int jj=0;jj<4;jj++){
                float2 pif = __half22float2(ph[2*jj]);
                float2 pgo = __half22float2(ph[2*jj+1]);
                float2 rif = __half22float2(rh[2*jj]);
                float2 rgo = __half22float2(rh[2*jj+1]);
                float4 bb = *(const float4*)&BP[4*(j+jj)];
                float iv = pif.x + rif.x + bb.x;
                float fv = pif.y + rif.y + bb.y;
                float gv = pgo.x + rgo.x + bb.z;
                float ov = pgo.y + rgo.y + bb.w;
                float c2 = sigmoidf_(fv)*c1a[jj] + sigmoidf_(iv)*tanhf_(gv);
                c2p[jj] = c2;
                h2p[jj] = sigmoidf_(ov)*tanhf_(c2);
            }
            storeh4(h2v, &g_h2f[(size_t)l*M_TOTAL*K_PAD2 + grow*K_PAD2 + j]);
            *(float4*)&g_c2[(size_t)l*M_TOTAL*100 + grow*100 + j] = c2v;
            if (l==0){
                if (emit_out) *(float4*)&g_out[grow*600 + 200 + j] = h2v;
                storeh4(h2v, &g_Af[grow*K_PAD + 200 + j]);
            } else if (l==1){
                if (emit_out) *(float4*)&g_out[grow*600 + 300 + j] = h2v;
                storeh4(h2v, &g_Af[grow*K_PAD + 300 + j]);
            }
        }
    }
}

// ---------------------------------------------------------------------------
__global__ void __launch_bounds__(256,1) gat1_att(
    const float* __restrict__ a1, float* __restrict__ out_att, float* __restrict__ out2)
{
    __shared__ __align__(16) float a1s[1200];
    __shared__ float ebuf[41];
    __shared__ float att[40];
    __shared__ float red[2];
    int b=blockIdx.x, tid=threadIdx.x, warp=tid>>5, lane=tid&31;
    for (int i=tid;i<1200;i+=256) a1s[i]=a1[i];
    __syncthreads();
    const __half* base = g_hGf + (size_t)b*24000;
    for (int t=warp;t<41;t+=8){
        const __half* rowp = (t<40)? base + t*600 : base;
        const float* av    = (t<40)? a1s          : a1s+600;
        float s=0.f;
        for (int kk=lane;kk<75;kk+=32){
            uint4 raw = *(const uint4*)(rowp + kk*8);
            __half2* hv = (__half2*)&raw;
            const float* ap = av + kk*8;
            float2 f0=__half22float2(hv[0]), f1=__half22float2(hv[1]);
            float2 f2=__half22float2(hv[2]), f3=__half22float2(hv[3]);
            s += f0.x*ap[0]+f0.y*ap[1]+f1.x*ap[2]+f1.y*ap[3]
               + f2.x*ap[4]+f2.y*ap[5]+f3.x*ap[6]+f3.y*ap[7];
        }
        #pragma unroll
        for (int o=16;o;o>>=1) s += __shfl_xor_sync(0xffffffffu, s, o);
        if (lane==0) ebuf[t]=s;
    }
    __syncthreads();
    if (tid<40){
        float x = ebuf[tid] + ebuf[40];
        ebuf[tid] = (x>0.f)? x : 0.2f*x;
    }
    __syncthreads();
    if (tid<32){
        float v = ebuf[tid];
        if (tid<8) v = fmaxf(v, ebuf[tid+32]);
        #pragma unroll
        for (int o=16;o;o>>=1) v = fmaxf(v, __shfl_xor_sync(0xffffffffu, v, o));
        if (tid==0) red[0]=v;
    }
    __syncthreads();
    if (tid<40) att[tid]=__expf(ebuf[tid]-red[0]);
    __syncthreads();
    if (tid<32){
        float v = att[tid] + ((tid<8)? att[tid+32] : 0.f);
        #pragma unroll
        for (int o=16;o;o>>=1) v += __shfl_xor_sync(0xffffffffu, v, o);
        if (tid==0) red[1]=1.f/v;
    }
    __syncthreads();
    if (tid<40) att[tid]=fmaxf(att[tid]*red[1]-0.001f, 0.f);
    __syncthreads();
    for (int f2=tid; f2<300; f2+=256){
        float ax=0.f, ay=0.f;
        const __half2* col = (const __half2*)base + f2;
        #pragma unroll 8
        for (int n=0;n<40;n++){
            float2 v = __half22float2(col[n*300]);
            ax += att[n]*v.x; ay += att[n]*v.y;
        }
        out_att[(size_t)b*600 + f2*2]     = ax;
        out_att[(size_t)b*600 + f2*2 + 1] = ay;
    }
    if ((b&1)==0){
        const float* srow = g_out + (size_t)b*40*600;
        float* drow = out2 + (size_t)(b>>1)*600;
        for (int f=tid;f<600;f+=256) drow[f]=srow[f];
    }
}

// ---------------------------------------------------------------------------
#define GAT2_SMEM ((4000 + 10000 + 4000)*4)
__global__ void __launch_bounds__(256,1) gat2_kernel(
    const float* __restrict__ W2, const float* __restrict__ a2,
    float* __restrict__ output_att, float* __restrict__ op2)
{
    extern __shared__ float sm[];
    float* ops = sm;
    float* Ws  = ops + 4000;
    float* hg  = Ws  + 10000;
    __shared__ float a2s[200];
    __shared__ float ebuf[41];
    __shared__ float att[40];
    __shared__ float red[2];
    int b=blockIdx.x, tid=threadIdx.x, warp=tid>>5, lane=tid&31;
    const float* src = g_op + (size_t)b*4000;
    for (int i=tid;i<4000;i+=256)  ops[i]=src[i];
    for (int i=tid;i<10000;i+=256) Ws[i]=W2[i];
    if (tid<200) a2s[tid]=a2[tid];
    __syncthreads();
    for (int i=tid;i<4000;i+=256){
        int n=i/100, o=i-n*100;
        float acc=0.f;
        #pragma unroll 4
        for (int k=0;k<100;k++) acc=fmaf(ops[n*100+k], Ws[k*100+o], acc);
        hg[i]=acc;
    }
    __syncthreads();
    for (int t=warp;t<41;t+=8){
        const float* rowp = (t<40)? hg + t*100 : hg;
        const float* av   = (t<40)? a2s        : a2s+100;
        float s=0.f;
        for (int k=lane;k<100;k+=32) s += rowp[k]*av[k];
        #pragma unroll
        for (int o=16;o;o>>=1) s += __shfl_xor_sync(0xffffffffu, s, o);
        if (lane==0) ebuf[t]=s;
    }
    __syncthreads();
    if (tid<40){
        float x = ebuf[tid] + ebuf[40];
        ebuf[tid] = (x>0.f)? x : 0.2f*x;
    }
    __syncthreads();
    if (tid<32){
        float v = ebuf[tid];
        if (tid<8) v = fmaxf(v, ebuf[tid+32]);
        #pragma unroll
        for (int o=16;o;o>>=1) v = fmaxf(v, __shfl_xor_sync(0xffffffffu, v, o));
        if (tid==0) red[0]=v;
    }
    __syncthreads();
    if (tid<40) att[tid]=__expf(ebuf[tid]-red[0]);
    __syncthreads();
    if (tid<32){
        float v = att[tid] + ((tid<8)? att[tid+32] : 0.f);
        #pragma unroll
        for (int o=16;o;o>>=1) v += __shfl_xor_sync(0xffffffffu, v, o);
        if (tid==0) red[1]=1.f/v;
    }
    __syncthreads();
    if (tid<40) att[tid]=fmaxf(att[tid]*red[1]-0.001f, 0.f);
    __syncthreads();
    if (tid<100){
        float acc=0.f;
        #pragma unroll 8
        for (int n=0;n<40;n++) acc += att[n]*hg[n*100+tid];
        output_att[(size_t)b*100+tid]=acc;
    }
    if ((b&1)==0){
        const float* srow = g_op + (size_t)b*40*100;
        float* drow = op2 + (size_t)(b>>1)*100;
        if (tid<100) drow[tid]=srow[tid];
    }
}

// ---------------------------------------------------------------------------
extern "C" void kernel_launch(void* const* d_in, const int* in_sizes, int n_in,
                              void* d_out, int out_size)
{
    const int*   bh    = (const int*)  d_in[0];
    const int*   br    = (const int*)  d_in[1];
    const int*   bt    = (const int*)  d_in[2];
    const float* ent   = (const float*)d_in[3];
    const float* rel   = (const float*)d_in[4];
    const float* ent1  = (const float*)d_in[5];
    const float* rel1  = (const float*)d_in[6];
    const float* Wih_f = (const float*)d_in[7];
    const float* Whh_f = (const float*)d_in[8];
    const float* b_f   = (const float*)d_in[9];
    const float* Wih_b = (const float*)d_in[10];
    const float* Whh_b = (const float*)d_in[11];
    const float* b_b   = (const float*)d_in[12];
    const float* Wih_p = (const float*)d_in[13];
    const float* Whh_p = (const float*)d_in[14];
    const float* b_p   = (const float*)d_in[15];
    const float* W1    = (const float*)d_in[16];
    const float* a1    = (const float*)d_in[17];
    const float* W2    = (const float*)d_in[18];
    const float* a2    = (const float*)d_in[19];

    float* out        = (float*)d_out;
    float* out2       = out;                          // [1024,600]
    float* out_att    = out + 1024*600;               // [2048,600]
    float* op2        = out + 1024*600 + 2048*600;    // [1024,100]
    float* output_att = op2 + 1024*100;               // [2048,100]

    cudaFuncSetAttribute(gat2_kernel, cudaFuncAttributeMaxDynamicSharedMemorySize, GAT2_SMEM);
    cudaFuncSetAttribute(mma_gemm,    cudaFuncAttributeMaxDynamicSharedMemorySize, MM_SMEM);
    cudaFuncSetAttribute(mma_f16,     cudaFuncAttributeMaxDynamicSharedMemorySize, MMF_SMEM);
    cudaFuncSetAttribute(mma_lstm3,   cudaFuncAttributeMaxDynamicSharedMemorySize, MMF_SMEM);

    convB_kernel<<<(600*600 + 255)/256, 256>>>(W1);
    convW6_kernel<<<(6*400*100 + 255)/256, 256>>>(Whh_f, Whh_b, Whh_p, Wih_f, Wih_b, Wih_p);
    bias_perm_kernel<<<(3*400 + 255)/256, 256>>>(b_f, b_b, b_p);
    convE_kernel<<<(2*(NENT+NRELS)*100 + 255)/256, 256>>>(ent, ent1, rel, rel1);

    dim3 pe(4, NENT_P/64, 3);
    mma_gemm<<<pe, 256, MM_SMEM>>>(2);
    dim3 pr(4, 4, 3);
    mma_gemm<<<pr, 256, MM_SMEM>>>(3);

    step1_kernel<<<(3*NENT*100 + 255)/256, 256>>>();

    mma_gemm<<<pe, 256, MM_SMEM>>>(4);

    step12_kernel<<<M_TOTAL/64, 256>>>(bh, br, bt);

    dim3 rg(4, M_TOTAL/64, 3);
    mma_lstm3<<<rg, 256, MMF_SMEM>>>(bh, bt);

    dim3 gg(5, M_TOTAL/64, 1);
    mma_f16<<<gg, 256, MMF_SMEM>>>();

    gat1_att<<<NGROUP, 256>>>(a1, out_att, out2);

    gat2_kernel<<<NGROUP, 256, GAT2_SMEM>>>(W2, a2, output_att, op2);

    (void)in_sizes; (void)n_in; (void)out_size;
}

// round 12
// speedup vs baseline: 1.1313x; 1.1313x over previous
#include <cuda_runtime.h>
#include <cuda_bf16.h>
#include <cuda_fp16.h>
#include <math.h>
#include <cstdint>

#define M_TOTAL 81920
#define NGROUP  2048
#define NENT    14541
#define NRELS   237
#define NENT_P  14592
#define K_PAD   640
#define K_PAD2  128

// ---------------- scratch (device globals) ----------------------------------
__device__ __half g_Pe[3][NENT*400];        // fp16 tables
__device__ __half g_Pr[3][NRELS*400];
__device__ __half g_R1[3][NENT*400];
__device__ float  g_h1c1[3][NENT*200];
__device__ float  g_c2[(size_t)3*M_TOTAL*100];
__device__ __align__(16) __half g_R2f[(size_t)3*M_TOTAL*400];
__device__ float  g_out[(size_t)M_TOTAL*600];
__device__ __align__(16) __half g_hGf[(size_t)M_TOTAL*600];
__device__ float  g_op [(size_t)M_TOTAL*100];
// fp16 GEMM operands (pads stay zero)
__device__ __align__(16) __half g_Af[(size_t)M_TOTAL*K_PAD];
__device__ __align__(16) __half g_BTf[640*K_PAD];
__device__ __align__(16) __half g_h2f[(size_t)3*M_TOTAL*K_PAD2];
__device__ __align__(16) __half g_Wf[3][512*K_PAD2];
// bf16 hi/lo splits for the accurate vocab-level GEMMs
__device__ __align__(16) __nv_bfloat16 g_WTh[6][512*K_PAD2];
__device__ __align__(16) __nv_bfloat16 g_WTl[6][512*K_PAD2];
__device__ __align__(16) __nv_bfloat16 g_Eh[2][NENT_P*K_PAD2];
__device__ __align__(16) __nv_bfloat16 g_El[2][NENT_P*K_PAD2];
__device__ __align__(16) __nv_bfloat16 g_Rh[2][256*K_PAD2];
__device__ __align__(16) __nv_bfloat16 g_Rl[2][256*K_PAD2];
__device__ __align__(16) __nv_bfloat16 g_h1h[3][NENT_P*K_PAD2];
__device__ __align__(16) __nv_bfloat16 g_h1l[3][NENT_P*K_PAD2];

__device__ __forceinline__ float sigmoidf_(float x){
    return __fdividef(1.f, 1.f + __expf(-x));
}
__device__ __forceinline__ float tanhf_(float x){
    float xc = fminf(fmaxf(x,-15.f),15.f);
    float e = __expf(2.f*xc);
    return __fdividef(e-1.f, e+1.f);
}
__device__ __forceinline__ void split2(float v, __nv_bfloat16* ph, __nv_bfloat16* pl){
    __nv_bfloat16 h = __float2bfloat16(v);
    *ph = h;
    *pl = __float2bfloat16(v - __bfloat162float(h));
}
__device__ __forceinline__ void storeh4(float4 v, __half* p){
    ((__half2*)p)[0] = __floats2half2_rn(v.x, v.y);
    ((__half2*)p)[1] = __floats2half2_rn(v.z, v.w);
}
__device__ __forceinline__ float4 loadh4(const __half* p){
    __half2 a = ((const __half2*)p)[0], b = ((const __half2*)p)[1];
    float2 fa=__half22float2(a), fb=__half22float2(b);
    return make_float4(fa.x,fa.y,fb.x,fb.y);
}

// ======================= MMA plumbing =======================================
__device__ __forceinline__ void cp16(unsigned saddr, const void* g){
    asm volatile("cp.async.cg.shared.global [%0], [%1], 16;" :: "r"(saddr), "l"(g));
}
__device__ __forceinline__ void cp_commit(){
    asm volatile("cp.async.commit_group;" ::: "memory");
}
template<int N> __device__ __forceinline__ void cp_wait(){
    asm volatile("cp.async.wait_group %0;" :: "n"(N) : "memory");
}
__device__ __forceinline__ void ldm4(uint32_t* r, unsigned addr){
    asm volatile("ldmatrix.sync.aligned.m8n8.x4.shared.b16 {%0,%1,%2,%3}, [%4];"
        : "=r"(r[0]), "=r"(r[1]), "=r"(r[2]), "=r"(r[3]) : "r"(addr));
}
__device__ __forceinline__ void mma16816(float* d, const uint32_t* a, uint32_t b0, uint32_t b1){
    asm volatile("mma.sync.aligned.m16n8k16.row.col.f32.bf16.bf16.f32 "
        "{%0,%1,%2,%3},{%4,%5,%6,%7},{%8,%9},{%0,%1,%2,%3};"
        : "+f"(d[0]), "+f"(d[1]), "+f"(d[2]), "+f"(d[3])
        : "r"(a[0]), "r"(a[1]), "r"(a[2]), "r"(a[3]), "r"(b0), "r"(b1));
}
__device__ __forceinline__ void mma16816h(float* d, const uint32_t* a, uint32_t b0, uint32_t b1){
    asm volatile("mma.sync.aligned.m16n8k16.row.col.f32.f16.f16.f32 "
        "{%0,%1,%2,%3},{%4,%5,%6,%7},{%8,%9},{%0,%1,%2,%3};"
        : "+f"(d[0]), "+f"(d[1]), "+f"(d[2]), "+f"(d[3])
        : "r"(a[0]), "r"(a[1]), "r"(a[2]), "r"(a[3]), "r"(b0), "r"(b1));
}

// ======================= fp16 single-pass GEMM ==============================
#define STG_F16 24576
#define MMF_SMEM (2*STG_F16)

__device__ __forceinline__ void stageF(unsigned sb,
    const __half* A, size_t lda, const __half* B, size_t ldb, int kcol, int tid)
{
    for (int i=tid;i<512;i+=256){
        int r=i>>3, c=i&7;
        unsigned off = (unsigned)((r*128 + c*16) ^ ((r&7)<<4));
        cp16(sb + off, A + (size_t)r*lda + kcol + c*8);
    }
    for (int i=tid;i<1024;i+=256){
        int r=i>>3, c=i&7;
        unsigned off = (unsigned)((r*128 + c*16) ^ ((r&7)<<4));
        cp16(sb + 8192 + off, B + (size_t)r*ldb + kcol + c*8);
    }
}

__global__ void __launch_bounds__(256,3) mma_f16(int which)
{
    extern __shared__ char smraw[];
    unsigned sbase;
    asm("{ .reg .u64 t; cvta.to.shared.u64 t, %1; cvt.u32.u64 %0, t; }" : "=r"(sbase) : "l"(smraw));
    int tid=threadIdx.x, wid=tid>>5, lane=tid&31;
    int wm = wid & 1, wn = wid >> 1;
    int ncol0 = blockIdx.x*128, mrow0 = blockIdx.y*64;
    int z = blockIdx.z;

    const __half *A, *B; __half* C; int Nv, ldc, nch; size_t lda, ldb;
    if (which==0){
        A = g_Af + (size_t)mrow0*K_PAD; B = g_BTf + (size_t)ncol0*K_PAD;
        C = g_hGf; Nv=600; ldc=600; nch=10; lda=K_PAD; ldb=K_PAD;
    } else {
        A = g_h2f + (size_t)z*M_TOTAL*K_PAD2 + (size_t)mrow0*K_PAD2;
        B = g_Wf[z] + (size_t)ncol0*K_PAD2;
        C = g_R2f + (size_t)z*M_TOTAL*400; Nv=400; ldc=400; nch=2; lda=K_PAD2; ldb=K_PAD2;
    }

    float acc[2][4][4];
    #pragma unroll
    for (int i=0;i<2;i++)
        #pragma unroll
        for (int j=0;j<4;j++)
            #pragma unroll
            for (int q=0;q<4;q++) acc[i][j][q]=0.f;

    stageF(sbase,           A,lda,B,ldb, 0,  tid); cp_commit();
    stageF(sbase + STG_F16, A,lda,B,ldb, 64, tid); cp_commit();

    int lr  = lane & 15;
    int lhb = (lane >> 4) << 4;

    for (int k=0;k<nch;k++){
        if (k < nch-1) cp_wait<1>(); else cp_wait<0>();
        __syncthreads();
        unsigned st = sbase + (unsigned)(k&1)*STG_F16;
        unsigned sA = st, sB = st+8192;
        #pragma unroll
        for (int kk=0;kk<4;kk++){
            int cb = kk*32 + lhb;
            uint32_t ah[2][4], bb[2][4];
            #pragma unroll
            for (int mt=0;mt<2;mt++){
                int r = wm*32 + mt*16 + lr;
                unsigned off = (unsigned)((r*128 + cb) ^ ((r&7)<<4));
                ldm4(ah[mt], sA + off);
            }
            #pragma unroll
            for (int ng=0;ng<2;ng++){
                int n = wn*32 + ng*16 + lr;
                unsigned off = (unsigned)((n*128 + cb) ^ ((n&7)<<4));
                ldm4(bb[ng], sB + off);
            }
            #pragma unroll
            for (int mt=0;mt<2;mt++){
                #pragma unroll
                for (int nt=0;nt<4;nt++){
                    int ng = nt>>1, s = nt&1;
                    mma16816h(acc[mt][nt], ah[mt], bb[ng][s], bb[ng][s+2]);
                }
            }
        }
        __syncthreads();
        if (k+2 < nch){
            stageF(st, A,lda,B,ldb, (k+2)*64, tid);
            cp_commit();
        }
    }
    #pragma unroll
    for (int mt=0;mt<2;mt++){
        int rbase = mrow0 + wm*32 + mt*16 + (lane>>2);
        #pragma unroll
        for (int nt=0;nt<4;nt++){
            int col = ncol0 + wn*32 + nt*8 + (lane&3)*2;
            if (col < Nv){
                *(__half2*)(C + (size_t)rbase*ldc + col)     = __floats2half2_rn(acc[mt][nt][0], acc[mt][nt][1]);
                *(__half2*)(C + (size_t)(rbase+8)*ldc + col) = __floats2half2_rn(acc[mt][nt][2], acc[mt][nt][3]);
            }
        }
    }
}

// ======================= bf16 3-term GEMM (vocab-level, fp16 out) ===========
#define STG_BYTES 49152
#define MM_SMEM   (2*STG_BYTES)

__device__ __forceinline__ void stageG(unsigned sb,
    const __nv_bfloat16* Ah, const __nv_bfloat16* Al, size_t lda, int mrow0, int Mv,
    const __nv_bfloat16* Bh, const __nv_bfloat16* Bl, size_t ldb, int ncol0,
    int kcol, int tid)
{
    for (int i=tid;i<512;i+=256){
        int r=i>>3, c=i&7;
        unsigned off = (unsigned)((r*128 + c*16) ^ ((r&7)<<4));
        int ra = mrow0 + r; if (ra >= Mv) ra = Mv-1;
        cp16(sb + off,         Ah + (size_t)ra*lda + kcol + c*8);
        cp16(sb + 8192 + off,  Al + (size_t)ra*lda + kcol + c*8);
    }
    for (int i=tid;i<1024;i+=256){
        int r=i>>3, c=i&7;
        unsigned off = (unsigned)((r*128 + c*16) ^ ((r&7)<<4));
        cp16(sb + 16384 + off,  Bh + (size_t)(ncol0+r)*ldb + kcol + c*8);
        cp16(sb + 32768 + off,  Bl + (size_t)(ncol0+r)*ldb + kcol + c*8);
    }
}

// which 2: Pe[z]  3: Pr[z]  4: R1[z]
__global__ void __launch_bounds__(256,2) mma_gemm(int which)
{
    extern __shared__ char smraw[];
    unsigned sbase;
    asm("{ .reg .u64 t; cvta.to.shared.u64 t, %1; cvt.u32.u64 %0, t; }" : "=r"(sbase) : "l"(smraw));

    const __nv_bfloat16 *Ah,*Al,*Bh,*Bl; __half* C;
    int Mv;
    int z = blockIdx.z;
    switch (which){
      case 2: {
        int e = (z==2)? 1 : 0;
        Ah=g_Eh[e]; Al=g_El[e]; Bh=g_WTh[3+z]; Bl=g_WTl[3+z]; C=g_Pe[z]; Mv=NENT; break; }
      case 3: {
        int e = (z==2)? 1 : 0;
        Ah=g_Rh[e]; Al=g_Rl[e]; Bh=g_WTh[3+z]; Bl=g_WTl[3+z]; C=g_Pr[z]; Mv=NRELS; break; }
      default:
        Ah=g_h1h[z]; Al=g_h1l[z]; Bh=g_WTh[z]; Bl=g_WTl[z]; C=g_R1[z]; Mv=NENT; break;
    }
    const int Nv=400, ldc=400, nch=2;
    const size_t lda=K_PAD2, ldb=K_PAD2;

    int tid=threadIdx.x, wid=tid>>5, lane=tid&31;
    int wm = wid & 1, wn = wid >> 1;
    int ncol0 = blockIdx.x*128, mrow0 = blockIdx.y*64;

    float acc[2][4][4];
    #pragma unroll
    for (int i=0;i<2;i++)
        #pragma unroll
        for (int j=0;j<4;j++)
            #pragma unroll
            for (int q=0;q<4;q++) acc[i][j][q]=0.f;

    stageG(sbase,             Ah,Al,lda,mrow0,Mv, Bh,Bl,ldb,ncol0, 0,  tid); cp_commit();
    stageG(sbase + STG_BYTES, Ah,Al,lda,mrow0,Mv, Bh,Bl,ldb,ncol0, 64, tid); cp_commit();

    int lr  = lane & 15;
    int lhb = (lane >> 4) << 4;

    for (int k=0;k<nch;k++){
        if (k < nch-1) cp_wait<1>(); else cp_wait<0>();
        __syncthreads();
        unsigned st = sbase + (unsigned)(k&1)*STG_BYTES;
        unsigned sAh = st, sAl = st+8192, sBh = st+16384, sBl = st+32768;

        #pragma unroll
        for (int kk=0;kk<4;kk++){
            int cb = kk*32 + lhb;
            uint32_t ah[2][4], al[2][4], bh[2][4], bl[2][4];
            #pragma unroll
            for (int mt=0;mt<2;mt++){
                int r = wm*32 + mt*16 + lr;
                unsigned off = (unsigned)((r*128 + cb) ^ ((r&7)<<4));
                ldm4(ah[mt], sAh + off);
                ldm4(al[mt], sAl + off);
            }
            #pragma unroll
            for (int ng=0;ng<2;ng++){
                int n = wn*32 + ng*16 + lr;
                unsigned off = (unsigned)((n*128 + cb) ^ ((n&7)<<4));
                ldm4(bh[ng], sBh + off);
                ldm4(bl[ng], sBl + off);
            }
            #pragma unroll
            for (int mt=0;mt<2;mt++){
                #pragma unroll
                for (int nt=0;nt<4;nt++){
                    int ng = nt>>1, s = nt&1;
                    mma16816(acc[mt][nt], ah[mt], bh[ng][s], bh[ng][s+2]);
                    mma16816(acc[mt][nt], ah[mt], bl[ng][s], bl[ng][s+2]);
                    mma16816(acc[mt][nt], al[mt], bh[ng][s], bh[ng][s+2]);
                }
            }
        }
        __syncthreads();
        if (k+2 < nch){
            stageG(st, Ah,Al,lda,mrow0,Mv, Bh,Bl,ldb,ncol0, (k+2)*64, tid);
            cp_commit();
        }
    }

    #pragma unroll
    for (int mt=0;mt<2;mt++){
        int rbase = mrow0 + wm*32 + mt*16 + (lane>>2);
        #pragma unroll
        for (int nt=0;nt<4;nt++){
            int col = ncol0 + wn*32 + nt*8 + (lane&3)*2;
            if (col < Nv){
                if (rbase < Mv)
                    *(__half2*)(C + (size_t)rbase*ldc + col)     = __floats2half2_rn(acc[mt][nt][0], acc[mt][nt][1]);
                if (rbase+8 < Mv)
                    *(__half2*)(C + (size_t)(rbase+8)*ldc + col) = __floats2half2_rn(acc[mt][nt][2], acc[mt][nt][3]);
            }
        }
    }
}

// ---------------------------------------------------------------------------
// conversions
// ---------------------------------------------------------------------------
__global__ void convB_kernel(const float* __restrict__ W1)
{
    int i = blockIdx.x*256 + threadIdx.x;
    if (i >= 600*600) return;
    int n = i / 600, k = i - n*600;
    g_BTf[(size_t)n*K_PAD + k] = __float2half(W1[(size_t)k*600 + n]);
}
__global__ void convW6_kernel(const float* __restrict__ Whf, const float* __restrict__ Whb,
                              const float* __restrict__ Whp, const float* __restrict__ Wif,
                              const float* __restrict__ Wib, const float* __restrict__ Wip)
{
    int i = blockIdx.x*256 + threadIdx.x;
    if (i >= 6*400*100) return;
    int m = i / 40000; int rem = i - m*40000;
    int n = rem/100, k = rem - n*100;
    const float* W;
    switch(m){ case 0:W=Whf;break; case 1:W=Whb;break; case 2:W=Whp;break;
               case 3:W=Wif;break; case 4:W=Wib;break; default:W=Wip;break; }
    float v = W[n*100+k];
    split2(v, &g_WTh[m][n*K_PAD2 + k], &g_WTl[m][n*K_PAD2 + k]);
    if (m < 3) g_Wf[m][n*K_PAD2 + k] = __float2half(v);
}
__global__ void convE_kernel(const float* __restrict__ ent, const float* __restrict__ ent1,
                             const float* __restrict__ rel, const float* __restrict__ rel1)
{
    int i = blockIdx.x*256 + threadIdx.x;
    if (i < 2*NENT*100){
        int e = i / (NENT*100); int rem = i - e*(NENT*100);
        int r = rem/100, k = rem - r*100;
        const float* src = e ? ent1 : ent;
        split2(src[(size_t)r*100+k], &g_Eh[e][(size_t)r*K_PAD2+k], &g_El[e][(size_t)r*K_PAD2+k]);
    } else {
        int j = i - 2*NENT*100;
        if (j >= 2*NRELS*100) return;
        int e = j / (NRELS*100); int rem = j - e*(NRELS*100);
        int r = rem/100, k = rem - r*100;
        const float* src = e ? rel1 : rel;
        split2(src[(size_t)r*100+k], &g_Rh[e][(size_t)r*K_PAD2+k], &g_Rl[e][(size_t)r*K_PAD2+k]);
    }
}

// ---------------------------------------------------------------------------
__global__ void step1_kernel(const float* __restrict__ b_f,
                             const float* __restrict__ b_b,
                             const float* __restrict__ b_p)
{
    int idx = blockIdx.x*256 + threadIdx.x;
    if (idx >= 3*NENT*100) return;
    int l   = idx / (NENT*100);
    int rem = idx - l*(NENT*100);
    int e = rem/100, j = rem - e*100;
    const __half* P = g_Pe[l] + (size_t)e*400;
    const float* b = (l==0)? b_f : (l==1)? b_b : b_p;
    float iv = __half2float(P[j])     + b[j];
    float gv = __half2float(P[200+j]) + b[200+j];
    float ov = __half2float(P[300+j]) + b[300+j];
    float c1 = sigmoidf_(iv) * tanhf_(gv);
    float h1 = sigmoidf_(ov) * tanhf_(c1);
    g_h1c1[l][(size_t)e*200 + j]       = h1;
    g_h1c1[l][(size_t)e*200 + 100 + j] = c1;
    split2(h1, &g_h1h[l][(size_t)e*K_PAD2 + j], &g_h1l[l][(size_t)e*K_PAD2 + j]);
}

// ---------------------------------------------------------------------------
__global__ void __launch_bounds__(256) step12_kernel(
    const int* __restrict__ bh, const int* __restrict__ br, const int* __restrict__ bt,
    const float* __restrict__ b_f, const float* __restrict__ b_b, const float* __restrict__ b_p)
{
    __shared__ int ih[64], ir[64], it[64];
    int tid=threadIdx.x; int row0=blockIdx.x*64;
    if (tid<64)        ih[tid]     = bh[row0+tid];
    else if (tid<128)  ir[tid-64]  = br[row0+tid-64];
    else if (tid<192)  it[tid-128] = bt[row0+tid-128];
    __syncthreads();
    for (int l=0;l<3;l++){
        const __half* Pr = g_Pr[l];
        const __half* R1 = g_R1[l];
        const float*  HC = g_h1c1[l];
        const float* bias= (l==0)?b_f:(l==1)?b_b:b_p;
        for (int t=tid;t<1600;t+=256){
            int row=t/25, q=t-row*25; int j=q*4;
            int fi = (l==1)? it[row] : ih[row];
            size_t grow=(size_t)(row0+row);
            bool emit_out = ((grow % 80u)==0u) && (l<2);
            float4 h1v = *(const float4*)&HC[(size_t)fi*200 + j];
            float4 c1v = *(const float4*)&HC[(size_t)fi*200 + 100 + j];
            if (l==0){
                if (emit_out) *(float4*)&g_out[grow*600 + j] = h1v;
                storeh4(h1v, &g_Af[grow*K_PAD + j]);
            } else if (l==1){
                if (emit_out) *(float4*)&g_out[grow*600 + 500 + j] = h1v;
                storeh4(h1v, &g_Af[grow*K_PAD + 500 + j]);
            }
            const __half* pr = Pr + (size_t)ir[row]*400;
            const __half* r1 = R1 + (size_t)fi*400;
            float4 pi = loadh4(pr+j),      ri = loadh4(r1+j);
            float4 pf = loadh4(pr+100+j),  rf = loadh4(r1+100+j);
            float4 pg = loadh4(pr+200+j),  rg = loadh4(r1+200+j);
            float4 po = loadh4(pr+300+j),  ro = loadh4(r1+300+j);
            float4 bi = *(const float4*)&bias[j],    bf4= *(const float4*)&bias[100+j];
            float4 bg = *(const float4*)&bias[200+j],bo = *(const float4*)&bias[300+j];
            float4 c2v, h2v;
            {
                float c,h;
                c = sigmoidf_(pf.x+rf.x+bf4.x)*c1v.x + sigmoidf_(pi.x+ri.x+bi.x)*tanhf_(pg.x+rg.x+bg.x);
                h = sigmoidf_(po.x+ro.x+bo.x)*tanhf_(c); c2v.x=c; h2v.x=h;
                c = sigmoidf_(pf.y+rf.y+bf4.y)*c1v.y + sigmoidf_(pi.y+ri.y+bi.y)*tanhf_(pg.y+rg.y+bg.y);
                h = sigmoidf_(po.y+ro.y+bo.y)*tanhf_(c); c2v.y=c; h2v.y=h;
                c = sigmoidf_(pf.z+rf.z+bf4.z)*c1v.z + sigmoidf_(pi.z+ri.z+bi.z)*tanhf_(pg.z+rg.z+bg.z);
                h = sigmoidf_(po.z+ro.z+bo.z)*tanhf_(c); c2v.z=c; h2v.z=h;
                c = sigmoidf_(pf.w+rf.w+bf4.w)*c1v.w + sigmoidf_(pi.w+ri.w+bi.w)*tanhf_(pg.w+rg.w+bg.w);
                h = sigmoidf_(po.w+ro.w+bo.w)*tanhf_(c); c2v.w=c; h2v.w=h;
            }
            storeh4(h2v, &g_h2f[(size_t)l*M_TOTAL*K_PAD2 + grow*K_PAD2 + j]);
            *(float4*)&g_c2[(size_t)l*M_TOTAL*100 + grow*100 + j] = c2v;
            if (l==0){
                if (emit_out) *(float4*)&g_out[grow*600 + 200 + j] = h2v;
                storeh4(h2v, &g_Af[grow*K_PAD + 200 + j]);
            } else if (l==1){
                if (emit_out) *(float4*)&g_out[grow*600 + 300 + j] = h2v;
                storeh4(h2v, &g_Af[grow*K_PAD + 300 + j]);
            }
        }
    }
}

// ---------------------------------------------------------------------------
__global__ void __launch_bounds__(256) step3_kernel(
    const int* __restrict__ bh, const int* __restrict__ bt,
    const float* __restrict__ b_f, const float* __restrict__ b_b, const float* __restrict__ b_p)
{
    __shared__ int ih[64], it[64];
    int tid=threadIdx.x; int row0=blockIdx.x*64;
    if (tid<64)        ih[tid]    = bh[row0+tid];
    else if (tid<128)  it[tid-64] = bt[row0+tid-64];
    __syncthreads();
    for (int l=0;l<3;l++){
        const __half* Pe = g_Pe[l];
        const __half* R2 = g_R2f + (size_t)l*M_TOTAL*400;
        const float*  C2 = g_c2 + (size_t)l*M_TOTAL*100;
        const float* bias= (l==0)?b_f:(l==1)?b_b:b_p;
        for (int t=tid;t<1600;t+=256){
            int row=t/25, q=t-row*25; int j=q*4;
            int li = (l==1)? ih[row] : it[row];
            size_t grow=(size_t)(row0+row);
            const __half* pe = Pe + (size_t)li*400;
            const __half* r2 = R2 + grow*400;
            float4 pi = loadh4(pe+j),      ri = loadh4(r2+j);
            float4 pf = loadh4(pe+100+j),  rf = loadh4(r2+100+j);
            float4 pg = loadh4(pe+200+j),  rg = loadh4(r2+200+j);
            float4 po = loadh4(pe+300+j),  ro = loadh4(r2+300+j);
            float4 bi = *(const float4*)&bias[j],    bf4= *(const float4*)&bias[100+j];
            float4 bg = *(const float4*)&bias[200+j],bo = *(const float4*)&bias[300+j];
            float4 c2v = *(const float4*)&C2[grow*100 + j];
            float4 h3v;
            {
                float c;
                c = sigmoidf_(pf.x+rf.x+bf4.x)*c2v.x + sigmoidf_(pi.x+ri.x+bi.x)*tanhf_(pg.x+rg.x+bg.x);
                h3v.x = sigmoidf_(po.x+ro.x+bo.x)*tanhf_(c);
                c = sigmoidf_(pf.y+rf.y+bf4.y)*c2v.y + sigmoidf_(pi.y+ri.y+bi.y)*tanhf_(pg.y+rg.y+bg.y);
                h3v.y = sigmoidf_(po.y+ro.y+bo.y)*tanhf_(c);
                c = sigmoidf_(pf.z+rf.z+bf4.z)*c2v.z + sigmoidf_(pi.z+ri.z+bi.z)*tanhf_(pg.z+rg.z+bg.z);
                h3v.z = sigmoidf_(po.z+ro.z+bo.z)*tanhf_(c);
                c = sigmoidf_(pf.w+rf.w+bf4.w)*c2v.w + sigmoidf_(pi.w+ri.w+bi.w)*tanhf_(pg.w+rg.w+bg.w);
                h3v.w = sigmoidf_(po.w+ro.w+bo.w)*tanhf_(c);
            }
            bool emit_out = ((grow % 80u)==0u);
            if (l==0){
                if (emit_out) *(float4*)&g_out[grow*600 + 400 + j] = h3v;
                storeh4(h3v, &g_Af[grow*K_PAD + 400 + j]);
            } else if (l==1){
                if (emit_out) *(float4*)&g_out[grow*600 + 100 + j] = h3v;
                storeh4(h3v, &g_Af[grow*K_PAD + 100 + j]);
            } else {
                *(float4*)&g_op[grow*100 + j] = h3v;
            }
        }
    }
}

// ---------------------------------------------------------------------------
// GAT1 attention: stage the 40x600 fp16 tile in smem (48KB), 2 CTAs/SM.
// ---------------------------------------------------------------------------
#define GAT1_SMEM (24000*2)
__global__ void __launch_bounds__(256,2) gat1_att(
    const float* __restrict__ a1, float* __restrict__ out_att, float* __restrict__ out2)
{
    extern __shared__ __align__(16) __half hgs[];   // 40*600 fp16 = 48000 B
    __shared__ __align__(16) float a1s[1200];
    __shared__ float ebuf[41];
    __shared__ float att[40];
    __shared__ float red[2];
    int b=blockIdx.x, tid=threadIdx.x, warp=tid>>5, lane=tid&31;
    const __half* base = g_hGf + (size_t)b*24000;
    for (int i=tid;i<3000;i+=256) ((uint4*)hgs)[i] = ((const uint4*)base)[i];
    for (int i=tid;i<1200;i+=256) a1s[i]=a1[i];
    __syncthreads();
    for (int t=warp;t<41;t+=8){
        const __half* rowp = (t<40)? hgs + t*600 : hgs;
        const float* av    = (t<40)? a1s         : a1s+600;
        float s=0.f;
        for (int kk=lane;kk<75;kk+=32){
            uint4 raw = *(const uint4*)(rowp + kk*8);
            __half2* hv = (__half2*)&raw;
            const float* ap = av + kk*8;
            float2 f0=__half22float2(hv[0]), f1=__half22float2(hv[1]);
            float2 f2=__half22float2(hv[2]), f3=__half22float2(hv[3]);
            s += f0.x*ap[0]+f0.y*ap[1]+f1.x*ap[2]+f1.y*ap[3]
               + f2.x*ap[4]+f2.y*ap[5]+f3.x*ap[6]+f3.y*ap[7];
        }
        #pragma unroll
        for (int o=16;o;o>>=1) s += __shfl_xor_sync(0xffffffffu, s, o);
        if (lane==0) ebuf[t]=s;
    }
    __syncthreads();
    if (tid<40){
        float x = ebuf[tid] + ebuf[40];
        ebuf[tid] = (x>0.f)? x : 0.2f*x;
    }
    __syncthreads();
    if (tid<32){
        float v = ebuf[tid];
        if (tid<8) v = fmaxf(v, ebuf[tid+32]);
        #pragma unroll
        for (int o=16;o;o>>=1) v = fmaxf(v, __shfl_xor_sync(0xffffffffu, v, o));
        if (tid==0) red[0]=v;
    }
    __syncthreads();
    if (tid<40) att[tid]=__expf(ebuf[tid]-red[0]);
    __syncthreads();
    if (tid<32){
        float v = att[tid] + ((tid<8)? att[tid+32] : 0.f);
        #pragma unroll
        for (int o=16;o;o>>=1) v += __shfl_xor_sync(0xffffffffu, v, o);
        if (tid==0) red[1]=1.f/v;
    }
    __syncthreads();
    if (tid<40) att[tid]=fmaxf(att[tid]*red[1]-0.001f, 0.f);
    __syncthreads();
    for (int f2=tid; f2<300; f2+=256){
        float ax=0.f, ay=0.f;
        const __half2* col = (const __half2*)hgs + f2;
        #pragma unroll 8
        for (int n=0;n<40;n++){
            float2 v = __half22float2(col[n*300]);
            ax += att[n]*v.x; ay += att[n]*v.y;
        }
        out_att[(size_t)b*600 + f2*2]     = ax;
        out_att[(size_t)b*600 + f2*2 + 1] = ay;
    }
    if ((b&1)==0){
        const float* srow = g_out + (size_t)b*40*600;
        float* drow = out2 + (size_t)(b>>1)*600;
        for (int f=tid;f<600;f+=256) drow[f]=srow[f];
    }
}

// ---------------------------------------------------------------------------
#define GAT2_SMEM ((4000 + 10000 + 4000)*4)
__global__ void __launch_bounds__(256,1) gat2_kernel(
    const float* __restrict__ W2, const float* __restrict__ a2,
    float* __restrict__ output_att, float* __restrict__ op2)
{
    extern __shared__ float sm[];
    float* ops = sm;
    float* Ws  = ops + 4000;
    float* hg  = Ws  + 10000;
    __shared__ float a2s[200];
    __shared__ float ebuf[41];
    __shared__ float att[40];
    __shared__ float red[2];
    int b=blockIdx.x, tid=threadIdx.x, warp=tid>>5, lane=tid&31;
    const float* src = g_op + (size_t)b*4000;
    for (int i=tid;i<4000;i+=256)  ops[i]=src[i];
    for (int i=tid;i<10000;i+=256) Ws[i]=W2[i];
    if (tid<200) a2s[tid]=a2[tid];
    __syncthreads();
    for (int i=tid;i<4000;i+=256){
        int n=i/100, o=i-n*100;
        float acc=0.f;
        #pragma unroll 4
        for (int k=0;k<100;k++) acc=fmaf(ops[n*100+k], Ws[k*100+o], acc);
        hg[i]=acc;
    }
    __syncthreads();
    for (int t=warp;t<41;t+=8){
        const float* rowp = (t<40)? hg + t*100 : hg;
        const float* av   = (t<40)? a2s        : a2s+100;
        float s=0.f;
        for (int k=lane;k<100;k+=32) s += rowp[k]*av[k];
        #pragma unroll
        for (int o=16;o;o>>=1) s += __shfl_xor_sync(0xffffffffu, s, o);
        if (lane==0) ebuf[t]=s;
    }
    __syncthreads();
    if (tid<40){
        float x = ebuf[tid] + ebuf[40];
        ebuf[tid] = (x>0.f)? x : 0.2f*x;
    }
    __syncthreads();
    if (tid<32){
        float v = ebuf[tid];
        if (tid<8) v = fmaxf(v, ebuf[tid+32]);
        #pragma unroll
        for (int o=16;o;o>>=1) v = fmaxf(v, __shfl_xor_sync(0xffffffffu, v, o));
        if (tid==0) red[0]=v;
    }
    __syncthreads();
    if (tid<40) att[tid]=__expf(ebuf[tid]-red[0]);
    __syncthreads();
    if (tid<32){
        float v = att[tid] + ((tid<8)? att[tid+32] : 0.f);
        #pragma unroll
        for (int o=16;o;o>>=1) v += __shfl_xor_sync(0xffffffffu, v, o);
        if (tid==0) red[1]=1.f/v;
    }
    __syncthreads();
    if (tid<40) att[tid]=fmaxf(att[tid]*red[1]-0.001f, 0.f);
    __syncthreads();
    if (tid<100){
        float acc=0.f;
        #pragma unroll 8
        for (int n=0;n<40;n++) acc += att[n]*hg[n*100+tid];
        output_att[(size_t)b*100+tid]=acc;
    }
    if ((b&1)==0){
        const float* srow = g_op + (size_t)b*40*100;
        float* drow = op2 + (size_t)(b>>1)*100;
        if (tid<100) drow[tid]=srow[tid];
    }
}

// ---------------------------------------------------------------------------
extern "C" void kernel_launch(void* const* d_in, const int* in_sizes, int n_in,
                              void* d_out, int out_size)
{
    const int*   bh    = (const int*)  d_in[0];
    const int*   br    = (const int*)  d_in[1];
    const int*   bt    = (const int*)  d_in[2];
    const float* ent   = (const float*)d_in[3];
    const float* rel   = (const float*)d_in[4];
    const float* ent1  = (const float*)d_in[5];
    const float* rel1  = (const float*)d_in[6];
    const float* Wih_f = (const float*)d_in[7];
    const float* Whh_f = (const float*)d_in[8];
    const float* b_f   = (const float*)d_in[9];
    const float* Wih_b = (const float*)d_in[10];
    const float* Whh_b = (const float*)d_in[11];
    const float* b_b   = (const float*)d_in[12];
    const float* Wih_p = (const float*)d_in[13];
    const float* Whh_p = (const float*)d_in[14];
    const float* b_p   = (const float*)d_in[15];
    const float* W1    = (const float*)d_in[16];
    const float* a1    = (const float*)d_in[17];
    const float* W2    = (const float*)d_in[18];
    const float* a2    = (const float*)d_in[19];

    float* out        = (float*)d_out;
    float* out2       = out;                          // [1024,600]
    float* out_att    = out + 1024*600;               // [2048,600]
    float* op2        = out + 1024*600 + 2048*600;    // [1024,100]
    float* output_att = op2 + 1024*100;               // [2048,100]

    cudaFuncSetAttribute(gat2_kernel, cudaFuncAttributeMaxDynamicSharedMemorySize, GAT2_SMEM);
    cudaFuncSetAttribute(gat1_att,    cudaFuncAttributeMaxDynamicSharedMemorySize, GAT1_SMEM);
    cudaFuncSetAttribute(mma_gemm,    cudaFuncAttributeMaxDynamicSharedMemorySize, MM_SMEM);
    cudaFuncSetAttribute(mma_f16,     cudaFuncAttributeMaxDynamicSharedMemorySize, MMF_SMEM);

    convB_kernel<<<(600*600 + 255)/256, 256>>>(W1);
    convW6_kernel<<<(6*400*100 + 255)/256, 256>>>(Whh_f, Whh_b, Whh_p, Wih_f, Wih_b, Wih_p);
    convE_kernel<<<(2*(NENT+NRELS)*100 + 255)/256, 256>>>(ent, ent1, rel, rel1);

    dim3 pe(4, NENT_P/64, 3);
    mma_gemm<<<pe, 256, MM_SMEM>>>(2);
    dim3 pr(4, 4, 3);
    mma_gemm<<<pr, 256, MM_SMEM>>>(3);

    step1_kernel<<<(3*NENT*100 + 255)/256, 256>>>(b_f, b_b, b_p);

    mma_gemm<<<pe, 256, MM_SMEM>>>(4);

    step12_kernel<<<M_TOTAL/64, 256>>>(bh, br, bt, b_f, b_b, b_p);

    dim3 rg(4, M_TOTAL/64, 3);
    mma_f16<<<rg, 256, MMF_SMEM>>>(1);

    step3_kernel<<<M_TOTAL/64, 256>>>(bh, bt, b_f, b_b, b_p);

    dim3 gg(5, M_TOTAL/64, 1);
    mma_f16<<<gg, 256, MMF_SMEM>>>(0);

    gat1_att<<<NGROUP, 256, GAT1_SMEM>>>(a1, out_att, out2);

    gat2_kernel<<<NGROUP, 256, GAT2_SMEM>>>(W2, a2, output_att, op2);

    (void)in_sizes; (void)n_in; (void)out_size;
}

// round 13
// speedup vs baseline: 1.1754x; 1.0390x over previous
#include <cuda_runtime.h>
#include <cuda_bf16.h>
#include <cuda_fp16.h>
#include <math.h>
#include <cstdint>

#define M_TOTAL 81920
#define NGROUP  2048
#define NENT    14541
#define NRELS   237
#define NENT_P  14592
#define K_PAD   640
#define K_PAD2  128

// ---------------- scratch (device globals) ----------------------------------
__device__ __half g_Pe[3][NENT*400];        // fp16 tables
__device__ __half g_Pr[3][NRELS*400];
__device__ __half g_R1[3][NENT*400];
__device__ float  g_h1c1[3][NENT*200];
__device__ float  g_c2[(size_t)3*M_TOTAL*100];
__device__ __align__(16) __half g_R2f[(size_t)3*M_TOTAL*400];
__device__ float  g_out[(size_t)M_TOTAL*600];
__device__ __align__(16) __half g_hGf[(size_t)M_TOTAL*600];
__device__ float  g_op [(size_t)M_TOTAL*100];
// fp16 GEMM operands (pads stay zero)
__device__ __align__(16) __half g_Af[(size_t)M_TOTAL*K_PAD];
__device__ __align__(16) __half g_BTf[640*K_PAD];
__device__ __align__(16) __half g_h2f[(size_t)3*M_TOTAL*K_PAD2];
__device__ __align__(16) __half g_Wf[3][512*K_PAD2];
// bf16 hi/lo splits for the accurate vocab-level GEMMs
__device__ __align__(16) __nv_bfloat16 g_WTh[6][512*K_PAD2];
__device__ __align__(16) __nv_bfloat16 g_WTl[6][512*K_PAD2];
__device__ __align__(16) __nv_bfloat16 g_Eh[2][NENT_P*K_PAD2];
__device__ __align__(16) __nv_bfloat16 g_El[2][NENT_P*K_PAD2];
__device__ __align__(16) __nv_bfloat16 g_Rh[2][256*K_PAD2];
__device__ __align__(16) __nv_bfloat16 g_Rl[2][256*K_PAD2];
__device__ __align__(16) __nv_bfloat16 g_h1h[3][NENT_P*K_PAD2];
__device__ __align__(16) __nv_bfloat16 g_h1l[3][NENT_P*K_PAD2];

__device__ __forceinline__ float sigmoidf_(float x){
    return __fdividef(1.f, 1.f + __expf(-x));
}
__device__ __forceinline__ float tanhf_(float x){
    float xc = fminf(fmaxf(x,-15.f),15.f);
    float e = __expf(2.f*xc);
    return __fdividef(e-1.f, e+1.f);
}
__device__ __forceinline__ void split2(float v, __nv_bfloat16* ph, __nv_bfloat16* pl){
    __nv_bfloat16 h = __float2bfloat16(v);
    *ph = h;
    *pl = __float2bfloat16(v - __bfloat162float(h));
}
__device__ __forceinline__ void storeh4(float4 v, __half* p){
    ((__half2*)p)[0] = __floats2half2_rn(v.x, v.y);
    ((__half2*)p)[1] = __floats2half2_rn(v.z, v.w);
}
__device__ __forceinline__ float4 loadh4(const __half* p){
    __half2 a = ((const __half2*)p)[0], b = ((const __half2*)p)[1];
    float2 fa=__half22float2(a), fb=__half22float2(b);
    return make_float4(fa.x,fa.y,fb.x,fb.y);
}

// ======================= MMA plumbing =======================================
__device__ __forceinline__ void cp16(unsigned saddr, const void* g){
    asm volatile("cp.async.cg.shared.global [%0], [%1], 16;" :: "r"(saddr), "l"(g));
}
__device__ __forceinline__ void cp_commit(){
    asm volatile("cp.async.commit_group;" ::: "memory");
}
template<int N> __device__ __forceinline__ void cp_wait(){
    asm volatile("cp.async.wait_group %0;" :: "n"(N) : "memory");
}
__device__ __forceinline__ void ldm4(uint32_t* r, unsigned addr){
    asm volatile("ldmatrix.sync.aligned.m8n8.x4.shared.b16 {%0,%1,%2,%3}, [%4];"
        : "=r"(r[0]), "=r"(r[1]), "=r"(r[2]), "=r"(r[3]) : "r"(addr));
}
__device__ __forceinline__ void mma16816(float* d, const uint32_t* a, uint32_t b0, uint32_t b1){
    asm volatile("mma.sync.aligned.m16n8k16.row.col.f32.bf16.bf16.f32 "
        "{%0,%1,%2,%3},{%4,%5,%6,%7},{%8,%9},{%0,%1,%2,%3};"
        : "+f"(d[0]), "+f"(d[1]), "+f"(d[2]), "+f"(d[3])
        : "r"(a[0]), "r"(a[1]), "r"(a[2]), "r"(a[3]), "r"(b0), "r"(b1));
}
__device__ __forceinline__ void mma16816h(float* d, const uint32_t* a, uint32_t b0, uint32_t b1){
    asm volatile("mma.sync.aligned.m16n8k16.row.col.f32.f16.f16.f32 "
        "{%0,%1,%2,%3},{%4,%5,%6,%7},{%8,%9},{%0,%1,%2,%3};"
        : "+f"(d[0]), "+f"(d[1]), "+f"(d[2]), "+f"(d[3])
        : "r"(a[0]), "r"(a[1]), "r"(a[2]), "r"(a[3]), "r"(b0), "r"(b1));
}

// ======================= fp16 single-pass GEMM ==============================
#define STG_F16 24576
#define MMF_SMEM (2*STG_F16)

__device__ __forceinline__ void stageF(unsigned sb,
    const __half* A, size_t lda, const __half* B, size_t ldb, int kcol, int tid)
{
    for (int i=tid;i<512;i+=256){
        int r=i>>3, c=i&7;
        unsigned off = (unsigned)((r*128 + c*16) ^ ((r&7)<<4));
        cp16(sb + off, A + (size_t)r*lda + kcol + c*8);
    }
    for (int i=tid;i<1024;i+=256){
        int r=i>>3, c=i&7;
        unsigned off = (unsigned)((r*128 + c*16) ^ ((r&7)<<4));
        cp16(sb + 8192 + off, B + (size_t)r*ldb + kcol + c*8);
    }
}

__global__ void __launch_bounds__(256,3) mma_f16(int which)
{
    extern __shared__ char smraw[];
    unsigned sbase;
    asm("{ .reg .u64 t; cvta.to.shared.u64 t, %1; cvt.u32.u64 %0, t; }" : "=r"(sbase) : "l"(smraw));
    int tid=threadIdx.x, wid=tid>>5, lane=tid&31;
    int wm = wid & 1, wn = wid >> 1;
    int ncol0 = blockIdx.x*128, mrow0 = blockIdx.y*64;
    int z = blockIdx.z;

    const __half *A, *B; __half* C; int Nv, ldc, nch; size_t lda, ldb;
    if (which==0){
        A = g_Af + (size_t)mrow0*K_PAD; B = g_BTf + (size_t)ncol0*K_PAD;
        C = g_hGf; Nv=600; ldc=600; nch=10; lda=K_PAD; ldb=K_PAD;
    } else {
        A = g_h2f + (size_t)z*M_TOTAL*K_PAD2 + (size_t)mrow0*K_PAD2;
        B = g_Wf[z] + (size_t)ncol0*K_PAD2;
        C = g_R2f + (size_t)z*M_TOTAL*400; Nv=400; ldc=400; nch=2; lda=K_PAD2; ldb=K_PAD2;
    }

    float acc[2][4][4];
    #pragma unroll
    for (int i=0;i<2;i++)
        #pragma unroll
        for (int j=0;j<4;j++)
            #pragma unroll
            for (int q=0;q<4;q++) acc[i][j][q]=0.f;

    stageF(sbase,           A,lda,B,ldb, 0,  tid); cp_commit();
    stageF(sbase + STG_F16, A,lda,B,ldb, 64, tid); cp_commit();

    int lr  = lane & 15;
    int lhb = (lane >> 4) << 4;

    for (int k=0;k<nch;k++){
        if (k < nch-1) cp_wait<1>(); else cp_wait<0>();
        __syncthreads();
        unsigned st = sbase + (unsigned)(k&1)*STG_F16;
        unsigned sA = st, sB = st+8192;
        #pragma unroll
        for (int kk=0;kk<4;kk++){
            int cb = kk*32 + lhb;
            uint32_t ah[2][4], bb[2][4];
            #pragma unroll
            for (int mt=0;mt<2;mt++){
                int r = wm*32 + mt*16 + lr;
                unsigned off = (unsigned)((r*128 + cb) ^ ((r&7)<<4));
                ldm4(ah[mt], sA + off);
            }
            #pragma unroll
            for (int ng=0;ng<2;ng++){
                int n = wn*32 + ng*16 + lr;
                unsigned off = (unsigned)((n*128 + cb) ^ ((n&7)<<4));
                ldm4(bb[ng], sB + off);
            }
            #pragma unroll
            for (int mt=0;mt<2;mt++){
                #pragma unroll
                for (int nt=0;nt<4;nt++){
                    int ng = nt>>1, s = nt&1;
                    mma16816h(acc[mt][nt], ah[mt], bb[ng][s], bb[ng][s+2]);
                }
            }
        }
        __syncthreads();
        if (k+2 < nch){
            stageF(st, A,lda,B,ldb, (k+2)*64, tid);
            cp_commit();
        }
    }
    #pragma unroll
    for (int mt=0;mt<2;mt++){
        int rbase = mrow0 + wm*32 + mt*16 + (lane>>2);
        #pragma unroll
        for (int nt=0;nt<4;nt++){
            int col = ncol0 + wn*32 + nt*8 + (lane&3)*2;
            if (col < Nv){
                *(__half2*)(C + (size_t)rbase*ldc + col)     = __floats2half2_rn(acc[mt][nt][0], acc[mt][nt][1]);
                *(__half2*)(C + (size_t)(rbase+8)*ldc + col) = __floats2half2_rn(acc[mt][nt][2], acc[mt][nt][3]);
            }
        }
    }
}

// ======================= bf16 3-term GEMM (vocab-level, fp16 out) ===========
#define STG_BYTES 49152
#define MM_SMEM   (2*STG_BYTES)

__device__ __forceinline__ void stageG(unsigned sb,
    const __nv_bfloat16* Ah, const __nv_bfloat16* Al, size_t lda, int mrow0, int Mv,
    const __nv_bfloat16* Bh, const __nv_bfloat16* Bl, size_t ldb, int ncol0,
    int kcol, int tid)
{
    for (int i=tid;i<512;i+=256){
        int r=i>>3, c=i&7;
        unsigned off = (unsigned)((r*128 + c*16) ^ ((r&7)<<4));
        int ra = mrow0 + r; if (ra >= Mv) ra = Mv-1;
        cp16(sb + off,         Ah + (size_t)ra*lda + kcol + c*8);
        cp16(sb + 8192 + off,  Al + (size_t)ra*lda + kcol + c*8);
    }
    for (int i=tid;i<1024;i+=256){
        int r=i>>3, c=i&7;
        unsigned off = (unsigned)((r*128 + c*16) ^ ((r&7)<<4));
        cp16(sb + 16384 + off,  Bh + (size_t)(ncol0+r)*ldb + kcol + c*8);
        cp16(sb + 32768 + off,  Bl + (size_t)(ncol0+r)*ldb + kcol + c*8);
    }
}

// which 2: Pe[z]  3: Pr[z]  4: R1[z]
__global__ void __launch_bounds__(256,2) mma_gemm(int which)
{
    extern __shared__ char smraw[];
    unsigned sbase;
    asm("{ .reg .u64 t; cvta.to.shared.u64 t, %1; cvt.u32.u64 %0, t; }" : "=r"(sbase) : "l"(smraw));

    const __nv_bfloat16 *Ah,*Al,*Bh,*Bl; __half* C;
    int Mv;
    int z = blockIdx.z;
    switch (which){
      case 2: {
        int e = (z==2)? 1 : 0;
        Ah=g_Eh[e]; Al=g_El[e]; Bh=g_WTh[3+z]; Bl=g_WTl[3+z]; C=g_Pe[z]; Mv=NENT; break; }
      case 3: {
        int e = (z==2)? 1 : 0;
        Ah=g_Rh[e]; Al=g_Rl[e]; Bh=g_WTh[3+z]; Bl=g_WTl[3+z]; C=g_Pr[z]; Mv=NRELS; break; }
      default:
        Ah=g_h1h[z]; Al=g_h1l[z]; Bh=g_WTh[z]; Bl=g_WTl[z]; C=g_R1[z]; Mv=NENT; break;
    }
    const int Nv=400, ldc=400, nch=2;
    const size_t lda=K_PAD2, ldb=K_PAD2;

    int tid=threadIdx.x, wid=tid>>5, lane=tid&31;
    int wm = wid & 1, wn = wid >> 1;
    int ncol0 = blockIdx.x*128, mrow0 = blockIdx.y*64;

    float acc[2][4][4];
    #pragma unroll
    for (int i=0;i<2;i++)
        #pragma unroll
        for (int j=0;j<4;j++)
            #pragma unroll
            for (int q=0;q<4;q++) acc[i][j][q]=0.f;

    stageG(sbase,             Ah,Al,lda,mrow0,Mv, Bh,Bl,ldb,ncol0, 0,  tid); cp_commit();
    stageG(sbase + STG_BYTES, Ah,Al,lda,mrow0,Mv, Bh,Bl,ldb,ncol0, 64, tid); cp_commit();

    int lr  = lane & 15;
    int lhb = (lane >> 4) << 4;

    for (int k=0;k<nch;k++){
        if (k < nch-1) cp_wait<1>(); else cp_wait<0>();
        __syncthreads();
        unsigned st = sbase + (unsigned)(k&1)*STG_BYTES;
        unsigned sAh = st, sAl = st+8192, sBh = st+16384, sBl = st+32768;

        #pragma unroll
        for (int kk=0;kk<4;kk++){
            int cb = kk*32 + lhb;
            uint32_t ah[2][4], al[2][4], bh[2][4], bl[2][4];
            #pragma unroll
            for (int mt=0;mt<2;mt++){
                int r = wm*32 + mt*16 + lr;
                unsigned off = (unsigned)((r*128 + cb) ^ ((r&7)<<4));
                ldm4(ah[mt], sAh + off);
                ldm4(al[mt], sAl + off);
            }
            #pragma unroll
            for (int ng=0;ng<2;ng++){
                int n = wn*32 + ng*16 + lr;
                unsigned off = (unsigned)((n*128 + cb) ^ ((n&7)<<4));
                ldm4(bh[ng], sBh + off);
                ldm4(bl[ng], sBl + off);
            }
            #pragma unroll
            for (int mt=0;mt<2;mt++){
                #pragma unroll
                for (int nt=0;nt<4;nt++){
                    int ng = nt>>1, s = nt&1;
                    mma16816(acc[mt][nt], ah[mt], bh[ng][s], bh[ng][s+2]);
                    mma16816(acc[mt][nt], ah[mt], bl[ng][s], bl[ng][s+2]);
                    mma16816(acc[mt][nt], al[mt], bh[ng][s], bh[ng][s+2]);
                }
            }
        }
        __syncthreads();
        if (k+2 < nch){
            stageG(st, Ah,Al,lda,mrow0,Mv, Bh,Bl,ldb,ncol0, (k+2)*64, tid);
            cp_commit();
        }
    }

    #pragma unroll
    for (int mt=0;mt<2;mt++){
        int rbase = mrow0 + wm*32 + mt*16 + (lane>>2);
        #pragma unroll
        for (int nt=0;nt<4;nt++){
            int col = ncol0 + wn*32 + nt*8 + (lane&3)*2;
            if (col < Nv){
                if (rbase < Mv)
                    *(__half2*)(C + (size_t)rbase*ldc + col)     = __floats2half2_rn(acc[mt][nt][0], acc[mt][nt][1]);
                if (rbase+8 < Mv)
                    *(__half2*)(C + (size_t)(rbase+8)*ldc + col) = __floats2half2_rn(acc[mt][nt][2], acc[mt][nt][3]);
            }
        }
    }
}

// ---------------------------------------------------------------------------
// conversions
// ---------------------------------------------------------------------------
__global__ void convB_kernel(const float* __restrict__ W1)
{
    int i = blockIdx.x*256 + threadIdx.x;
    if (i >= 600*600) return;
    int n = i / 600, k = i - n*600;
    g_BTf[(size_t)n*K_PAD + k] = __float2half(W1[(size_t)k*600 + n]);
}
__global__ void convW6_kernel(const float* __restrict__ Whf, const float* __restrict__ Whb,
                              const float* __restrict__ Whp, const float* __restrict__ Wif,
                              const float* __restrict__ Wib, const float* __restrict__ Wip)
{
    int i = blockIdx.x*256 + threadIdx.x;
    if (i >= 6*400*100) return;
    int m = i / 40000; int rem = i - m*40000;
    int n = rem/100, k = rem - n*100;
    const float* W;
    switch(m){ case 0:W=Whf;break; case 1:W=Whb;break; case 2:W=Whp;break;
               case 3:W=Wif;break; case 4:W=Wib;break; default:W=Wip;break; }
    float v = W[n*100+k];
    split2(v, &g_WTh[m][n*K_PAD2 + k], &g_WTl[m][n*K_PAD2 + k]);
    if (m < 3) g_Wf[m][n*K_PAD2 + k] = __float2half(v);
}
__global__ void convE_kernel(const float* __restrict__ ent, const float* __restrict__ ent1,
                             const float* __restrict__ rel, const float* __restrict__ rel1)
{
    int i = blockIdx.x*256 + threadIdx.x;
    if (i < 2*NENT*100){
        int e = i / (NENT*100); int rem = i - e*(NENT*100);
        int r = rem/100, k = rem - r*100;
        const float* src = e ? ent1 : ent;
        split2(src[(size_t)r*100+k], &g_Eh[e][(size_t)r*K_PAD2+k], &g_El[e][(size_t)r*K_PAD2+k]);
    } else {
        int j = i - 2*NENT*100;
        if (j >= 2*NRELS*100) return;
        int e = j / (NRELS*100); int rem = j - e*(NRELS*100);
        int r = rem/100, k = rem - r*100;
        const float* src = e ? rel1 : rel;
        split2(src[(size_t)r*100+k], &g_Rh[e][(size_t)r*K_PAD2+k], &g_Rl[e][(size_t)r*K_PAD2+k]);
    }
}

// ---------------------------------------------------------------------------
__global__ void step1_kernel(const float* __restrict__ b_f,
                             const float* __restrict__ b_b,
                             const float* __restrict__ b_p)
{
    int idx = blockIdx.x*256 + threadIdx.x;
    if (idx >= 3*NENT*100) return;
    int l   = idx / (NENT*100);
    int rem = idx - l*(NENT*100);
    int e = rem/100, j = rem - e*100;
    const __half* P = g_Pe[l] + (size_t)e*400;
    const float* b = (l==0)? b_f : (l==1)? b_b : b_p;
    float iv = __half2float(P[j])     + b[j];
    float gv = __half2float(P[200+j]) + b[200+j];
    float ov = __half2float(P[300+j]) + b[300+j];
    float c1 = sigmoidf_(iv) * tanhf_(gv);
    float h1 = sigmoidf_(ov) * tanhf_(c1);
    g_h1c1[l][(size_t)e*200 + j]       = h1;
    g_h1c1[l][(size_t)e*200 + 100 + j] = c1;
    split2(h1, &g_h1h[l][(size_t)e*K_PAD2 + j], &g_h1l[l][(size_t)e*K_PAD2 + j]);
}

// ---------------------------------------------------------------------------
// step12: one layer per blockIdx.y (3x parallelism vs fused-layer version)
// ---------------------------------------------------------------------------
__global__ void __launch_bounds__(256) step12_kernel(
    const int* __restrict__ bh, const int* __restrict__ br, const int* __restrict__ bt,
    const float* __restrict__ b_f, const float* __restrict__ b_b, const float* __restrict__ b_p)
{
    __shared__ int ifr[64], ir[64];
    int tid=threadIdx.x; int row0=blockIdx.x*64;
    int l = blockIdx.y;
    if (tid<64)        ifr[tid]    = (l==1)? bt[row0+tid] : bh[row0+tid];
    else if (tid<128)  ir[tid-64]  = br[row0+tid-64];
    __syncthreads();
    const __half* Pr = g_Pr[l];
    const __half* R1 = g_R1[l];
    const float*  HC = g_h1c1[l];
    const float* bias= (l==0)?b_f:(l==1)?b_b:b_p;
    for (int t=tid;t<1600;t+=256){
        int row=t/25, q=t-row*25; int j=q*4;
        int fi = ifr[row];
        size_t grow=(size_t)(row0+row);
        bool emit_out = ((grow % 80u)==0u) && (l<2);
        float4 h1v = *(const float4*)&HC[(size_t)fi*200 + j];
        float4 c1v = *(const float4*)&HC[(size_t)fi*200 + 100 + j];
        if (l==0){
            if (emit_out) *(float4*)&g_out[grow*600 + j] = h1v;
            storeh4(h1v, &g_Af[grow*K_PAD + j]);
        } else if (l==1){
            if (emit_out) *(float4*)&g_out[grow*600 + 500 + j] = h1v;
            storeh4(h1v, &g_Af[grow*K_PAD + 500 + j]);
        }
        const __half* pr = Pr + (size_t)ir[row]*400;
        const __half* r1 = R1 + (size_t)fi*400;
        float4 pi = loadh4(pr+j),      riv = loadh4(r1+j);
        float4 pf = loadh4(pr+100+j),  rf  = loadh4(r1+100+j);
        float4 pg = loadh4(pr+200+j),  rg  = loadh4(r1+200+j);
        float4 po = loadh4(pr+300+j),  ro  = loadh4(r1+300+j);
        float4 bi = *(const float4*)&bias[j],    bf4= *(const float4*)&bias[100+j];
        float4 bg = *(const float4*)&bias[200+j],bo = *(const float4*)&bias[300+j];
        float4 c2v, h2v;
        {
            float c,h;
            c = sigmoidf_(pf.x+rf.x+bf4.x)*c1v.x + sigmoidf_(pi.x+riv.x+bi.x)*tanhf_(pg.x+rg.x+bg.x);
            h = sigmoidf_(po.x+ro.x+bo.x)*tanhf_(c); c2v.x=c; h2v.x=h;
            c = sigmoidf_(pf.y+rf.y+bf4.y)*c1v.y + sigmoidf_(pi.y+riv.y+bi.y)*tanhf_(pg.y+rg.y+bg.y);
            h = sigmoidf_(po.y+ro.y+bo.y)*tanhf_(c); c2v.y=c; h2v.y=h;
            c = sigmoidf_(pf.z+rf.z+bf4.z)*c1v.z + sigmoidf_(pi.z+riv.z+bi.z)*tanhf_(pg.z+rg.z+bg.z);
            h = sigmoidf_(po.z+ro.z+bo.z)*tanhf_(c); c2v.z=c; h2v.z=h;
            c = sigmoidf_(pf.w+rf.w+bf4.w)*c1v.w + sigmoidf_(pi.w+riv.w+bi.w)*tanhf_(pg.w+rg.w+bg.w);
            h = sigmoidf_(po.w+ro.w+bo.w)*tanhf_(c); c2v.w=c; h2v.w=h;
        }
        storeh4(h2v, &g_h2f[(size_t)l*M_TOTAL*K_PAD2 + grow*K_PAD2 + j]);
        *(float4*)&g_c2[(size_t)l*M_TOTAL*100 + grow*100 + j] = c2v;
        if (l==0){
            if (emit_out) *(float4*)&g_out[grow*600 + 200 + j] = h2v;
            storeh4(h2v, &g_Af[grow*K_PAD + 200 + j]);
        } else if (l==1){
            if (emit_out) *(float4*)&g_out[grow*600 + 300 + j] = h2v;
            storeh4(h2v, &g_Af[grow*K_PAD + 300 + j]);
        }
    }
}

// ---------------------------------------------------------------------------
// step3: one layer per blockIdx.y
// ---------------------------------------------------------------------------
__global__ void __launch_bounds__(256) step3_kernel(
    const int* __restrict__ bh, const int* __restrict__ bt,
    const float* __restrict__ b_f, const float* __restrict__ b_b, const float* __restrict__ b_p)
{
    __shared__ int ila[64];
    int tid=threadIdx.x; int row0=blockIdx.x*64;
    int l = blockIdx.y;
    if (tid<64) ila[tid] = (l==1)? bh[row0+tid] : bt[row0+tid];
    __syncthreads();
    const __half* Pe = g_Pe[l];
    const __half* R2 = g_R2f + (size_t)l*M_TOTAL*400;
    const float*  C2 = g_c2 + (size_t)l*M_TOTAL*100;
    const float* bias= (l==0)?b_f:(l==1)?b_b:b_p;
    for (int t=tid;t<1600;t+=256){
        int row=t/25, q=t-row*25; int j=q*4;
        int li = ila[row];
        size_t grow=(size_t)(row0+row);
        const __half* pe = Pe + (size_t)li*400;
        const __half* r2 = R2 + grow*400;
        float4 pi = loadh4(pe+j),      riv = loadh4(r2+j);
        float4 pf = loadh4(pe+100+j),  rf  = loadh4(r2+100+j);
        float4 pg = loadh4(pe+200+j),  rg  = loadh4(r2+200+j);
        float4 po = loadh4(pe+300+j),  ro  = loadh4(r2+300+j);
        float4 bi = *(const float4*)&bias[j],    bf4= *(const float4*)&bias[100+j];
        float4 bg = *(const float4*)&bias[200+j],bo = *(const float4*)&bias[300+j];
        float4 c2v = *(const float4*)&C2[grow*100 + j];
        float4 h3v;
        {
            float c;
            c = sigmoidf_(pf.x+rf.x+bf4.x)*c2v.x + sigmoidf_(pi.x+riv.x+bi.x)*tanhf_(pg.x+rg.x+bg.x);
            h3v.x = sigmoidf_(po.x+ro.x+bo.x)*tanhf_(c);
            c = sigmoidf_(pf.y+rf.y+bf4.y)*c2v.y + sigmoidf_(pi.y+riv.y+bi.y)*tanhf_(pg.y+rg.y+bg.y);
            h3v.y = sigmoidf_(po.y+ro.y+bo.y)*tanhf_(c);
            c = sigmoidf_(pf.z+rf.z+bf4.z)*c2v.z + sigmoidf_(pi.z+riv.z+bi.z)*tanhf_(pg.z+rg.z+bg.z);
            h3v.z = sigmoidf_(po.z+ro.z+bo.z)*tanhf_(c);
            c = sigmoidf_(pf.w+rf.w+bf4.w)*c2v.w + sigmoidf_(pi.w+riv.w+bi.w)*tanhf_(pg.w+rg.w+bg.w);
            h3v.w = sigmoidf_(po.w+ro.w+bo.w)*tanhf_(c);
        }
        bool emit_out = ((grow % 80u)==0u);
        if (l==0){
            if (emit_out) *(float4*)&g_out[grow*600 + 400 + j] = h3v;
            storeh4(h3v, &g_Af[grow*K_PAD + 400 + j]);
        } else if (l==1){
            if (emit_out) *(float4*)&g_out[grow*600 + 100 + j] = h3v;
            storeh4(h3v, &g_Af[grow*K_PAD + 100 + j]);
        } else {
            *(float4*)&g_op[grow*100 + j] = h3v;
        }
    }
}

// ---------------------------------------------------------------------------
// GAT1 attention (R9 streaming form: reads g_hGf from L2 twice)
// ---------------------------------------------------------------------------
__global__ void __launch_bounds__(256,1) gat1_att(
    const float* __restrict__ a1, float* __restrict__ out_att, float* __restrict__ out2)
{
    __shared__ __align__(16) float a1s[1200];
    __shared__ float ebuf[41];
    __shared__ float att[40];
    __shared__ float red[2];
    int b=blockIdx.x, tid=threadIdx.x, warp=tid>>5, lane=tid&31;
    for (int i=tid;i<1200;i+=256) a1s[i]=a1[i];
    __syncthreads();
    const __half* base = g_hGf + (size_t)b*24000;
    for (int t=warp;t<41;t+=8){
        const __half* rowp = (t<40)? base + t*600 : base;
        const float* av    = (t<40)? a1s          : a1s+600;
        float s=0.f;
        for (int kk=lane;kk<75;kk+=32){
            uint4 raw = *(const uint4*)(rowp + kk*8);
            __half2* hv = (__half2*)&raw;
            const float* ap = av + kk*8;
            float2 f0=__half22float2(hv[0]), f1=__half22float2(hv[1]);
            float2 f2=__half22float2(hv[2]), f3=__half22float2(hv[3]);
            s += f0.x*ap[0]+f0.y*ap[1]+f1.x*ap[2]+f1.y*ap[3]
               + f2.x*ap[4]+f2.y*ap[5]+f3.x*ap[6]+f3.y*ap[7];
        }
        #pragma unroll
        for (int o=16;o;o>>=1) s += __shfl_xor_sync(0xffffffffu, s, o);
        if (lane==0) ebuf[t]=s;
    }
    __syncthreads();
    if (tid<40){
        float x = ebuf[tid] + ebuf[40];
        ebuf[tid] = (x>0.f)? x : 0.2f*x;
    }
    __syncthreads();
    if (tid<32){
        float v = ebuf[tid];
        if (tid<8) v = fmaxf(v, ebuf[tid+32]);
        #pragma unroll
        for (int o=16;o;o>>=1) v = fmaxf(v, __shfl_xor_sync(0xffffffffu, v, o));
        if (tid==0) red[0]=v;
    }
    __syncthreads();
    if (tid<40) att[tid]=__expf(ebuf[tid]-red[0]);
    __syncthreads();
    if (tid<32){
        float v = att[tid] + ((tid<8)? att[tid+32] : 0.f);
        #pragma unroll
        for (int o=16;o;o>>=1) v += __shfl_xor_sync(0xffffffffu, v, o);
        if (tid==0) red[1]=1.f/v;
    }
    __syncthreads();
    if (tid<40) att[tid]=fmaxf(att[tid]*red[1]-0.001f, 0.f);
    __syncthreads();
    for (int f2=tid; f2<300; f2+=256){
        float ax=0.f, ay=0.f;
        const __half2* col = (const __half2*)base + f2;
        #pragma unroll 8
        for (int n=0;n<40;n++){
            float2 v = __half22float2(col[n*300]);
            ax += att[n]*v.x; ay += att[n]*v.y;
        }
        out_att[(size_t)b*600 + f2*2]     = ax;
        out_att[(size_t)b*600 + f2*2 + 1] = ay;
    }
    if ((b&1)==0){
        const float* srow = g_out + (size_t)b*40*600;
        float* drow = out2 + (size_t)(b>>1)*600;
        for (int f=tid;f<600;f+=256) drow[f]=srow[f];
    }
}

// ---------------------------------------------------------------------------
#define GAT2_SMEM ((4000 + 10000 + 4000)*4)
__global__ void __launch_bounds__(256,1) gat2_kernel(
    const float* __restrict__ W2, const float* __restrict__ a2,
    float* __restrict__ output_att, float* __restrict__ op2)
{
    extern __shared__ float sm[];
    float* ops = sm;
    float* Ws  = ops + 4000;
    float* hg  = Ws  + 10000;
    __shared__ float a2s[200];
    __shared__ float ebuf[41];
    __shared__ float att[40];
    __shared__ float red[2];
    int b=blockIdx.x, tid=threadIdx.x, warp=tid>>5, lane=tid&31;
    const float* src = g_op + (size_t)b*4000;
    for (int i=tid;i<4000;i+=256)  ops[i]=src[i];
    for (int i=tid;i<10000;i+=256) Ws[i]=W2[i];
    if (tid<200) a2s[tid]=a2[tid];
    __syncthreads();
    for (int i=tid;i<4000;i+=256){
        int n=i/100, o=i-n*100;
        float acc=0.f;
        #pragma unroll 4
        for (int k=0;k<100;k++) acc=fmaf(ops[n*100+k], Ws[k*100+o], acc);
        hg[i]=acc;
    }
    __syncthreads();
    for (int t=warp;t<41;t+=8){
        const float* rowp = (t<40)? hg + t*100 : hg;
        const float* av   = (t<40)? a2s        : a2s+100;
        float s=0.f;
        for (int k=lane;k<100;k+=32) s += rowp[k]*av[k];
        #pragma unroll
        for (int o=16;o;o>>=1) s += __shfl_xor_sync(0xffffffffu, s, o);
        if (lane==0) ebuf[t]=s;
    }
    __syncthreads();
    if (tid<40){
        float x = ebuf[tid] + ebuf[40];
        ebuf[tid] = (x>0.f)? x : 0.2f*x;
    }
    __syncthreads();
    if (tid<32){
        float v = ebuf[tid];
        if (tid<8) v = fmaxf(v, ebuf[tid+32]);
        #pragma unroll
        for (int o=16;o;o>>=1) v = fmaxf(v, __shfl_xor_sync(0xffffffffu, v, o));
        if (tid==0) red[0]=v;
    }
    __syncthreads();
    if (tid<40) att[tid]=__expf(ebuf[tid]-red[0]);
    __syncthreads();
    if (tid<32){
        float v = att[tid] + ((tid<8)? att[tid+32] : 0.f);
        #pragma unroll
        for (int o=16;o;o>>=1) v += __shfl_xor_sync(0xffffffffu, v, o);
        if (tid==0) red[1]=1.f/v;
    }
    __syncthreads();
    if (tid<40) att[tid]=fmaxf(att[tid]*red[1]-0.001f, 0.f);
    __syncthreads();
    if (tid<100){
        float acc=0.f;
        #pragma unroll 8
        for (int n=0;n<40;n++) acc += att[n]*hg[n*100+tid];
        output_att[(size_t)b*100+tid]=acc;
    }
    if ((b&1)==0){
        const float* srow = g_op + (size_t)b*40*100;
        float* drow = op2 + (size_t)(b>>1)*100;
        if (tid<100) drow[tid]=srow[tid];
    }
}

// ---------------------------------------------------------------------------
extern "C" void kernel_launch(void* const* d_in, const int* in_sizes, int n_in,
                              void* d_out, int out_size)
{
    const int*   bh    = (const int*)  d_in[0];
    const int*   br    = (const int*)  d_in[1];
    const int*   bt    = (const int*)  d_in[2];
    const float* ent   = (const float*)d_in[3];
    const float* rel   = (const float*)d_in[4];
    const float* ent1  = (const float*)d_in[5];
    const float* rel1  = (const float*)d_in[6];
    const float* Wih_f = (const float*)d_in[7];
    const float* Whh_f = (const float*)d_in[8];
    const float* b_f   = (const float*)d_in[9];
    const float* Wih_b = (const float*)d_in[10];
    const float* Whh_b = (const float*)d_in[11];
    const float* b_b   = (const float*)d_in[12];
    const float* Wih_p = (const float*)d_in[13];
    const float* Whh_p = (const float*)d_in[14];
    const float* b_p   = (const float*)d_in[15];
    const float* W1    = (const float*)d_in[16];
    const float* a1    = (const float*)d_in[17];
    const float* W2    = (const float*)d_in[18];
    const float* a2    = (const float*)d_in[19];

    float* out        = (float*)d_out;
    float* out2       = out;                          // [1024,600]
    float* out_att    = out + 1024*600;               // [2048,600]
    float* op2        = out + 1024*600 + 2048*600;    // [1024,100]
    float* output_att = op2 + 1024*100;               // [2048,100]

    cudaFuncSetAttribute(gat2_kernel, cudaFuncAttributeMaxDynamicSharedMemorySize, GAT2_SMEM);
    cudaFuncSetAttribute(mma_gemm,    cudaFuncAttributeMaxDynamicSharedMemorySize, MM_SMEM);
    cudaFuncSetAttribute(mma_f16,     cudaFuncAttributeMaxDynamicSharedMemorySize, MMF_SMEM);

    convB_kernel<<<(600*600 + 255)/256, 256>>>(W1);
    convW6_kernel<<<(6*400*100 + 255)/256, 256>>>(Whh_f, Whh_b, Whh_p, Wih_f, Wih_b, Wih_p);
    convE_kernel<<<(2*(NENT+NRELS)*100 + 255)/256, 256>>>(ent, ent1, rel, rel1);

    dim3 pe(4, NENT_P/64, 3);
    mma_gemm<<<pe, 256, MM_SMEM>>>(2);
    dim3 pr(4, 4, 3);
    mma_gemm<<<pr, 256, MM_SMEM>>>(3);

    step1_kernel<<<(3*NENT*100 + 255)/256, 256>>>(b_f, b_b, b_p);

    mma_gemm<<<pe, 256, MM_SMEM>>>(4);

    dim3 sg(M_TOTAL/64, 3);
    step12_kernel<<<sg, 256>>>(bh, br, bt, b_f, b_b, b_p);

    dim3 rg(4, M_TOTAL/64, 3);
    mma_f16<<<rg, 256, MMF_SMEM>>>(1);

    step3_kernel<<<sg, 256>>>(bh, bt, b_f, b_b, b_p);

    dim3 gg(5, M_TOTAL/64, 1);
    mma_f16<<<gg, 256, MMF_SMEM>>>(0);

    gat1_att<<<NGROUP, 256>>>(a1, out_att, out2);

    gat2_kernel<<<NGROUP, 256, GAT2_SMEM>>>(W2, a2, output_att, op2);

    (void)in_sizes; (void)n_in; (void)out_size;
}

// round 14
// speedup vs baseline: 1.2139x; 1.0328x over previous
#include <cuda_runtime.h>
#include <cuda_fp16.h>
#include <math.h>
#include <cstdint>

#define M_TOTAL 81920
#define NGROUP  2048
#define NENT    14541
#define NRELS   237
#define NENT_P  14592
#define K_PAD   640
#define K_PAD2  128

// ---------------- scratch (device globals) ----------------------------------
__device__ __half g_Pe[3][NENT*400];        // fp16 gate tables
__device__ __half g_Pr[3][NRELS*400];
__device__ __half g_R1[3][NENT*400];
__device__ float  g_h1c1[3][NENT*200];
__device__ float  g_c2[(size_t)3*M_TOTAL*100];
__device__ __align__(16) __half g_R2f[(size_t)3*M_TOTAL*400];
__device__ float  g_out[(size_t)M_TOTAL*600];
__device__ __align__(16) __half g_hGf[(size_t)M_TOTAL*600];
__device__ float  g_op [(size_t)M_TOTAL*100];
// fp16 GEMM operands (pads stay zero)
__device__ __align__(16) __half g_Af[(size_t)M_TOTAL*K_PAD];
__device__ __align__(16) __half g_BTf[640*K_PAD];
__device__ __align__(16) __half g_h2f[(size_t)3*M_TOTAL*K_PAD2];
__device__ __align__(16) __half g_Wf[6][512*K_PAD2];   // 0..2 Whh, 3..5 Wih
__device__ __align__(16) __half g_Ef[2][NENT_P*K_PAD2];
__device__ __align__(16) __half g_Rf2[2][256*K_PAD2];
__device__ __align__(16) __half g_h1f[3][NENT_P*K_PAD2];

__device__ __forceinline__ float sigmoidf_(float x){
    return __fdividef(1.f, 1.f + __expf(-x));
}
__device__ __forceinline__ float tanhf_(float x){
    float xc = fminf(fmaxf(x,-15.f),15.f);
    float e = __expf(2.f*xc);
    return __fdividef(e-1.f, e+1.f);
}
__device__ __forceinline__ void storeh4(float4 v, __half* p){
    ((__half2*)p)[0] = __floats2half2_rn(v.x, v.y);
    ((__half2*)p)[1] = __floats2half2_rn(v.z, v.w);
}
__device__ __forceinline__ float4 loadh4(const __half* p){
    __half2 a = ((const __half2*)p)[0], b = ((const __half2*)p)[1];
    float2 fa=__half22float2(a), fb=__half22float2(b);
    return make_float4(fa.x,fa.y,fb.x,fb.y);
}

// ======================= MMA plumbing =======================================
__device__ __forceinline__ void cp16(unsigned saddr, const void* g){
    asm volatile("cp.async.cg.shared.global [%0], [%1], 16;" :: "r"(saddr), "l"(g));
}
__device__ __forceinline__ void cp_commit(){
    asm volatile("cp.async.commit_group;" ::: "memory");
}
template<int N> __device__ __forceinline__ void cp_wait(){
    asm volatile("cp.async.wait_group %0;" :: "n"(N) : "memory");
}
__device__ __forceinline__ void ldm4(uint32_t* r, unsigned addr){
    asm volatile("ldmatrix.sync.aligned.m8n8.x4.shared.b16 {%0,%1,%2,%3}, [%4];"
        : "=r"(r[0]), "=r"(r[1]), "=r"(r[2]), "=r"(r[3]) : "r"(addr));
}
__device__ __forceinline__ void mma16816h(float* d, const uint32_t* a, uint32_t b0, uint32_t b1){
    asm volatile("mma.sync.aligned.m16n8k16.row.col.f32.f16.f16.f32 "
        "{%0,%1,%2,%3},{%4,%5,%6,%7},{%8,%9},{%0,%1,%2,%3};"
        : "+f"(d[0]), "+f"(d[1]), "+f"(d[2]), "+f"(d[3])
        : "r"(a[0]), "r"(a[1]), "r"(a[2]), "r"(a[3]), "r"(b0), "r"(b1));
}

// ======================= fp16 single-pass GEMM ==============================
// tile 64(M) x 128(N), stage 24KB (A 8K | B 16K), 2 stages, 3 CTAs/SM.
// which 0: g_hGf = Af @ BTf^T (nch=10)
// which 1: g_R2f[z] = h2f[z] @ Wf[z]^T
// which 2: g_Pe[z] = Ef @ Wf[3+z]^T   3: g_Pr[z] = Rf2 @ Wf[3+z]^T
// which 4: g_R1[z] = h1f[z] @ Wf[z]^T
#define STG_F16 24576
#define MMF_SMEM (2*STG_F16)

__device__ __forceinline__ void stageF(unsigned sb,
    const __half* A, size_t lda, int mrow0, int Mv,
    const __half* B, size_t ldb, int kcol, int tid)
{
    for (int i=tid;i<512;i+=256){
        int r=i>>3, c=i&7;
        unsigned off = (unsigned)((r*128 + c*16) ^ ((r&7)<<4));
        int ra = mrow0 + r; if (ra >= Mv) ra = Mv-1;
        cp16(sb + off, A + (size_t)ra*lda + kcol + c*8);
    }
    for (int i=tid;i<1024;i+=256){
        int r=i>>3, c=i&7;
        unsigned off = (unsigned)((r*128 + c*16) ^ ((r&7)<<4));
        cp16(sb + 8192 + off, B + (size_t)r*ldb + kcol + c*8);
    }
}

__global__ void __launch_bounds__(256,3) mma_f16(int which)
{
    extern __shared__ char smraw[];
    unsigned sbase;
    asm("{ .reg .u64 t; cvta.to.shared.u64 t, %1; cvt.u32.u64 %0, t; }" : "=r"(sbase) : "l"(smraw));
    int tid=threadIdx.x, wid=tid>>5, lane=tid&31;
    int wm = wid & 1, wn = wid >> 1;
    int ncol0 = blockIdx.x*128, mrow0 = blockIdx.y*64;
    int z = blockIdx.z;

    const __half *A, *B; __half* C; int Nv, ldc, nch, Mv; size_t lda, ldb;
    switch (which){
      case 0:
        A = g_Af; B = g_BTf + (size_t)ncol0*K_PAD;
        C = g_hGf; Nv=600; ldc=600; nch=10; lda=K_PAD; ldb=K_PAD; Mv=M_TOTAL; break;
      case 1:
        A = g_h2f + (size_t)z*M_TOTAL*K_PAD2;
        B = g_Wf[z] + (size_t)ncol0*K_PAD2;
        C = g_R2f + (size_t)z*M_TOTAL*400;
        Nv=400; ldc=400; nch=2; lda=K_PAD2; ldb=K_PAD2; Mv=M_TOTAL; break;
      case 2: {
        int e = (z==2)? 1 : 0;
        A = g_Ef[e]; B = g_Wf[3+z] + (size_t)ncol0*K_PAD2; C = g_Pe[z];
        Nv=400; ldc=400; nch=2; lda=K_PAD2; ldb=K_PAD2; Mv=NENT; break; }
      case 3: {
        int e = (z==2)? 1 : 0;
        A = g_Rf2[e]; B = g_Wf[3+z] + (size_t)ncol0*K_PAD2; C = g_Pr[z];
        Nv=400; ldc=400; nch=2; lda=K_PAD2; ldb=K_PAD2; Mv=NRELS; break; }
      default:
        A = g_h1f[z]; B = g_Wf[z] + (size_t)ncol0*K_PAD2; C = g_R1[z];
        Nv=400; ldc=400; nch=2; lda=K_PAD2; ldb=K_PAD2; Mv=NENT; break;
    }

    float acc[2][4][4];
    #pragma unroll
    for (int i=0;i<2;i++)
        #pragma unroll
        for (int j=0;j<4;j++)
            #pragma unroll
            for (int q=0;q<4;q++) acc[i][j][q]=0.f;

    stageF(sbase,           A,lda,mrow0,Mv, B,ldb, 0,  tid); cp_commit();
    stageF(sbase + STG_F16, A,lda,mrow0,Mv, B,ldb, 64, tid); cp_commit();

    int lr  = lane & 15;
    int lhb = (lane >> 4) << 4;

    for (int k=0;k<nch;k++){
        if (k < nch-1) cp_wait<1>(); else cp_wait<0>();
        __syncthreads();
        unsigned st = sbase + (unsigned)(k&1)*STG_F16;
        unsigned sA = st, sB = st+8192;
        #pragma unroll
        for (int kk=0;kk<4;kk++){
            int cb = kk*32 + lhb;
            uint32_t ah[2][4], bb[2][4];
            #pragma unroll
            for (int mt=0;mt<2;mt++){
                int r = wm*32 + mt*16 + lr;
                unsigned off = (unsigned)((r*128 + cb) ^ ((r&7)<<4));
                ldm4(ah[mt], sA + off);
            }
            #pragma unroll
            for (int ng=0;ng<2;ng++){
                int n = wn*32 + ng*16 + lr;
                unsigned off = (unsigned)((n*128 + cb) ^ ((n&7)<<4));
                ldm4(bb[ng], sB + off);
            }
            #pragma unroll
            for (int mt=0;mt<2;mt++){
                #pragma unroll
                for (int nt=0;nt<4;nt++){
                    int ng = nt>>1, s = nt&1;
                    mma16816h(acc[mt][nt], ah[mt], bb[ng][s], bb[ng][s+2]);
                }
            }
        }
        __syncthreads();
        if (k+2 < nch){
            stageF(st, A,lda,mrow0,Mv, B,ldb, (k+2)*64, tid);
            cp_commit();
        }
    }
    #pragma unroll
    for (int mt=0;mt<2;mt++){
        int rbase = mrow0 + wm*32 + mt*16 + (lane>>2);
        #pragma unroll
        for (int nt=0;nt<4;nt++){
            int col = ncol0 + wn*32 + nt*8 + (lane&3)*2;
            if (col < Nv){
                if (rbase < Mv)
                    *(__half2*)(C + (size_t)rbase*ldc + col)     = __floats2half2_rn(acc[mt][nt][0], acc[mt][nt][1]);
                if (rbase+8 < Mv)
                    *(__half2*)(C + (size_t)(rbase+8)*ldc + col) = __floats2half2_rn(acc[mt][nt][2], acc[mt][nt][3]);
            }
        }
    }
}

// ---------------------------------------------------------------------------
// conversions (all fp16 now)
// ---------------------------------------------------------------------------
__global__ void convB_kernel(const float* __restrict__ W1)
{
    int i = blockIdx.x*256 + threadIdx.x;
    if (i >= 600*600) return;
    int n = i / 600, k = i - n*600;
    g_BTf[(size_t)n*K_PAD + k] = __float2half(W1[(size_t)k*600 + n]);
}
__global__ void convW6_kernel(const float* __restrict__ Whf, const float* __restrict__ Whb,
                              const float* __restrict__ Whp, const float* __restrict__ Wif,
                              const float* __restrict__ Wib, const float* __restrict__ Wip)
{
    int i = blockIdx.x*256 + threadIdx.x;
    if (i >= 6*400*100) return;
    int m = i / 40000; int rem = i - m*40000;
    int n = rem/100, k = rem - n*100;
    const float* W;
    switch(m){ case 0:W=Whf;break; case 1:W=Whb;break; case 2:W=Whp;break;
               case 3:W=Wif;break; case 4:W=Wib;break; default:W=Wip;break; }
    g_Wf[m][n*K_PAD2 + k] = __float2half(W[n*100+k]);
}
__global__ void convE_kernel(const float* __restrict__ ent, const float* __restrict__ ent1,
                             const float* __restrict__ rel, const float* __restrict__ rel1)
{
    int i = blockIdx.x*256 + threadIdx.x;
    if (i < 2*NENT*100){
        int e = i / (NENT*100); int rem = i - e*(NENT*100);
        int r = rem/100, k = rem - r*100;
        const float* src = e ? ent1 : ent;
        g_Ef[e][(size_t)r*K_PAD2+k] = __float2half(src[(size_t)r*100+k]);
    } else {
        int j = i - 2*NENT*100;
        if (j >= 2*NRELS*100) return;
        int e = j / (NRELS*100); int rem = j - e*(NRELS*100);
        int r = rem/100, k = rem - r*100;
        const float* src = e ? rel1 : rel;
        g_Rf2[e][(size_t)r*K_PAD2+k] = __float2half(src[(size_t)r*100+k]);
    }
}

// ---------------------------------------------------------------------------
__global__ void step1_kernel(const float* __restrict__ b_f,
                             const float* __restrict__ b_b,
                             const float* __restrict__ b_p)
{
    int idx = blockIdx.x*256 + threadIdx.x;
    if (idx >= 3*NENT*100) return;
    int l   = idx / (NENT*100);
    int rem = idx - l*(NENT*100);
    int e = rem/100, j = rem - e*100;
    const __half* P = g_Pe[l] + (size_t)e*400;
    const float* b = (l==0)? b_f : (l==1)? b_b : b_p;
    float iv = __half2float(P[j])     + b[j];
    float gv = __half2float(P[200+j]) + b[200+j];
    float ov = __half2float(P[300+j]) + b[300+j];
    float c1 = sigmoidf_(iv) * tanhf_(gv);
    float h1 = sigmoidf_(ov) * tanhf_(c1);
    g_h1c1[l][(size_t)e*200 + j]       = h1;
    g_h1c1[l][(size_t)e*200 + 100 + j] = c1;
    g_h1f[l][(size_t)e*K_PAD2 + j] = __float2half(h1);
}

// ---------------------------------------------------------------------------
// step12: one layer per blockIdx.y
// ---------------------------------------------------------------------------
__global__ void __launch_bounds__(256) step12_kernel(
    const int* __restrict__ bh, const int* __restrict__ br, const int* __restrict__ bt,
    const float* __restrict__ b_f, const float* __restrict__ b_b, const float* __restrict__ b_p)
{
    __shared__ int ifr[64], ir[64];
    int tid=threadIdx.x; int row0=blockIdx.x*64;
    int l = blockIdx.y;
    if (tid<64)        ifr[tid]    = (l==1)? bt[row0+tid] : bh[row0+tid];
    else if (tid<128)  ir[tid-64]  = br[row0+tid-64];
    __syncthreads();
    const __half* Pr = g_Pr[l];
    const __half* R1 = g_R1[l];
    const float*  HC = g_h1c1[l];
    const float* bias= (l==0)?b_f:(l==1)?b_b:b_p;
    for (int t=tid;t<1600;t+=256){
        int row=t/25, q=t-row*25; int j=q*4;
        int fi = ifr[row];
        size_t grow=(size_t)(row0+row);
        bool emit_out = ((grow % 80u)==0u) && (l<2);
        float4 h1v = *(const float4*)&HC[(size_t)fi*200 + j];
        float4 c1v = *(const float4*)&HC[(size_t)fi*200 + 100 + j];
        if (l==0){
            if (emit_out) *(float4*)&g_out[grow*600 + j] = h1v;
            storeh4(h1v, &g_Af[grow*K_PAD + j]);
        } else if (l==1){
            if (emit_out) *(float4*)&g_out[grow*600 + 500 + j] = h1v;
            storeh4(h1v, &g_Af[grow*K_PAD + 500 + j]);
        }
        const __half* pr = Pr + (size_t)ir[row]*400;
        const __half* r1 = R1 + (size_t)fi*400;
        float4 pi = loadh4(pr+j),      riv = loadh4(r1+j);
        float4 pf = loadh4(pr+100+j),  rf  = loadh4(r1+100+j);
        float4 pg = loadh4(pr+200+j),  rg  = loadh4(r1+200+j);
        float4 po = loadh4(pr+300+j),  ro  = loadh4(r1+300+j);
        float4 bi = *(const float4*)&bias[j],    bf4= *(const float4*)&bias[100+j];
        float4 bg = *(const float4*)&bias[200+j],bo = *(const float4*)&bias[300+j];
        float4 c2v, h2v;
        {
            float c,h;
            c = sigmoidf_(pf.x+rf.x+bf4.x)*c1v.x + sigmoidf_(pi.x+riv.x+bi.x)*tanhf_(pg.x+rg.x+bg.x);
            h = sigmoidf_(po.x+ro.x+bo.x)*tanhf_(c); c2v.x=c; h2v.x=h;
            c = sigmoidf_(pf.y+rf.y+bf4.y)*c1v.y + sigmoidf_(pi.y+riv.y+bi.y)*tanhf_(pg.y+rg.y+bg.y);
            h = sigmoidf_(po.y+ro.y+bo.y)*tanhf_(c); c2v.y=c; h2v.y=h;
            c = sigmoidf_(pf.z+rf.z+bf4.z)*c1v.z + sigmoidf_(pi.z+riv.z+bi.z)*tanhf_(pg.z+rg.z+bg.z);
            h = sigmoidf_(po.z+ro.z+bo.z)*tanhf_(c); c2v.z=c; h2v.z=h;
            c = sigmoidf_(pf.w+rf.w+bf4.w)*c1v.w + sigmoidf_(pi.w+riv.w+bi.w)*tanhf_(pg.w+rg.w+bg.w);
            h = sigmoidf_(po.w+ro.w+bo.w)*tanhf_(c); c2v.w=c; h2v.w=h;
        }
        storeh4(h2v, &g_h2f[(size_t)l*M_TOTAL*K_PAD2 + grow*K_PAD2 + j]);
        *(float4*)&g_c2[(size_t)l*M_TOTAL*100 + grow*100 + j] = c2v;
        if (l==0){
            if (emit_out) *(float4*)&g_out[grow*600 + 200 + j] = h2v;
            storeh4(h2v, &g_Af[grow*K_PAD + 200 + j]);
        } else if (l==1){
            if (emit_out) *(float4*)&g_out[grow*600 + 300 + j] = h2v;
            storeh4(h2v, &g_Af[grow*K_PAD + 300 + j]);
        }
    }
}

// ---------------------------------------------------------------------------
// step3: one layer per blockIdx.y
// ---------------------------------------------------------------------------
__global__ void __launch_bounds__(256) step3_kernel(
    const int* __restrict__ bh, const int* __restrict__ bt,
    const float* __restrict__ b_f, const float* __restrict__ b_b, const float* __restrict__ b_p)
{
    __shared__ int ila[64];
    int tid=threadIdx.x; int row0=blockIdx.x*64;
    int l = blockIdx.y;
    if (tid<64) ila[tid] = (l==1)? bh[row0+tid] : bt[row0+tid];
    __syncthreads();
    const __half* Pe = g_Pe[l];
    const __half* R2 = g_R2f + (size_t)l*M_TOTAL*400;
    const float*  C2 = g_c2 + (size_t)l*M_TOTAL*100;
    const float* bias= (l==0)?b_f:(l==1)?b_b:b_p;
    for (int t=tid;t<1600;t+=256){
        int row=t/25, q=t-row*25; int j=q*4;
        int li = ila[row];
        size_t grow=(size_t)(row0+row);
        const __half* pe = Pe + (size_t)li*400;
        const __half* r2 = R2 + grow*400;
        float4 pi = loadh4(pe+j),      riv = loadh4(r2+j);
        float4 pf = loadh4(pe+100+j),  rf  = loadh4(r2+100+j);
        float4 pg = loadh4(pe+200+j),  rg  = loadh4(r2+200+j);
        float4 po = loadh4(pe+300+j),  ro  = loadh4(r2+300+j);
        float4 bi = *(const float4*)&bias[j],    bf4= *(const float4*)&bias[100+j];
        float4 bg = *(const float4*)&bias[200+j],bo = *(const float4*)&bias[300+j];
        float4 c2v = *(const float4*)&C2[grow*100 + j];
        float4 h3v;
        {
            float c;
            c = sigmoidf_(pf.x+rf.x+bf4.x)*c2v.x + sigmoidf_(pi.x+riv.x+bi.x)*tanhf_(pg.x+rg.x+bg.x);
            h3v.x = sigmoidf_(po.x+ro.x+bo.x)*tanhf_(c);
            c = sigmoidf_(pf.y+rf.y+bf4.y)*c2v.y + sigmoidf_(pi.y+riv.y+bi.y)*tanhf_(pg.y+rg.y+bg.y);
            h3v.y = sigmoidf_(po.y+ro.y+bo.y)*tanhf_(c);
            c = sigmoidf_(pf.z+rf.z+bf4.z)*c2v.z + sigmoidf_(pi.z+riv.z+bi.z)*tanhf_(pg.z+rg.z+bg.z);
            h3v.z = sigmoidf_(po.z+ro.z+bo.z)*tanhf_(c);
            c = sigmoidf_(pf.w+rf.w+bf4.w)*c2v.w + sigmoidf_(pi.w+riv.w+bi.w)*tanhf_(pg.w+rg.w+bg.w);
            h3v.w = sigmoidf_(po.w+ro.w+bo.w)*tanhf_(c);
        }
        bool emit_out = ((grow % 80u)==0u);
        if (l==0){
            if (emit_out) *(float4*)&g_out[grow*600 + 400 + j] = h3v;
            storeh4(h3v, &g_Af[grow*K_PAD + 400 + j]);
        } else if (l==1){
            if (emit_out) *(float4*)&g_out[grow*600 + 100 + j] = h3v;
            storeh4(h3v, &g_Af[grow*K_PAD + 100 + j]);
        } else {
            *(float4*)&g_op[grow*100 + j] = h3v;
        }
    }
}

// ---------------------------------------------------------------------------
// GAT1 attention (streaming form)
// ---------------------------------------------------------------------------
__global__ void __launch_bounds__(256,1) gat1_att(
    const float* __restrict__ a1, float* __restrict__ out_att, float* __restrict__ out2)
{
    __shared__ __align__(16) float a1s[1200];
    __shared__ float ebuf[41];
    __shared__ float att[40];
    __shared__ float red[2];
    int b=blockIdx.x, tid=threadIdx.x, warp=tid>>5, lane=tid&31;
    for (int i=tid;i<1200;i+=256) a1s[i]=a1[i];
    __syncthreads();
    const __half* base = g_hGf + (size_t)b*24000;
    for (int t=warp;t<41;t+=8){
        const __half* rowp = (t<40)? base + t*600 : base;
        const float* av    = (t<40)? a1s          : a1s+600;
        float s=0.f;
        for (int kk=lane;kk<75;kk+=32){
            uint4 raw = *(const uint4*)(rowp + kk*8);
            __half2* hv = (__half2*)&raw;
            const float* ap = av + kk*8;
            float2 f0=__half22float2(hv[0]), f1=__half22float2(hv[1]);
            float2 f2=__half22float2(hv[2]), f3=__half22float2(hv[3]);
            s += f0.x*ap[0]+f0.y*ap[1]+f1.x*ap[2]+f1.y*ap[3]
               + f2.x*ap[4]+f2.y*ap[5]+f3.x*ap[6]+f3.y*ap[7];
        }
        #pragma unroll
        for (int o=16;o;o>>=1) s += __shfl_xor_sync(0xffffffffu, s, o);
        if (lane==0) ebuf[t]=s;
    }
    __syncthreads();
    if (tid<40){
        float x = ebuf[tid] + ebuf[40];
        ebuf[tid] = (x>0.f)? x : 0.2f*x;
    }
    __syncthreads();
    if (tid<32){
        float v = ebuf[tid];
        if (tid<8) v = fmaxf(v, ebuf[tid+32]);
        #pragma unroll
        for (int o=16;o;o>>=1) v = fmaxf(v, __shfl_xor_sync(0xffffffffu, v, o));
        if (tid==0) red[0]=v;
    }
    __syncthreads();
    if (tid<40) att[tid]=__expf(ebuf[tid]-red[0]);
    __syncthreads();
    if (tid<32){
        float v = att[tid] + ((tid<8)? att[tid+32] : 0.f);
        #pragma unroll
        for (int o=16;o;o>>=1) v += __shfl_xor_sync(0xffffffffu, v, o);
        if (tid==0) red[1]=1.f/v;
    }
    __syncthreads();
    if (tid<40) att[tid]=fmaxf(att[tid]*red[1]-0.001f, 0.f);
    __syncthreads();
    for (int f2=tid; f2<300; f2+=256){
        float ax=0.f, ay=0.f;
        const __half2* col = (const __half2*)base + f2;
        #pragma unroll 8
        for (int n=0;n<40;n++){
            float2 v = __half22float2(col[n*300]);
            ax += att[n]*v.x; ay += att[n]*v.y;
        }
        out_att[(size_t)b*600 + f2*2]     = ax;
        out_att[(size_t)b*600 + f2*2 + 1] = ay;
    }
    if ((b&1)==0){
        const float* srow = g_out + (size_t)b*40*600;
        float* drow = out2 + (size_t)(b>>1)*600;
        for (int f=tid;f<600;f+=256) drow[f]=srow[f];
    }
}

// ---------------------------------------------------------------------------
#define GAT2_SMEM ((4000 + 10000 + 4000)*4)
__global__ void __launch_bounds__(256,1) gat2_kernel(
    const float* __restrict__ W2, const float* __restrict__ a2,
    float* __restrict__ output_att, float* __restrict__ op2)
{
    extern __shared__ float sm[];
    float* ops = sm;
    float* Ws  = ops + 4000;
    float* hg  = Ws  + 10000;
    __shared__ float a2s[200];
    __shared__ float ebuf[41];
    __shared__ float att[40];
    __shared__ float red[2];
    int b=blockIdx.x, tid=threadIdx.x, warp=tid>>5, lane=tid&31;
    const float* src = g_op + (size_t)b*4000;
    for (int i=tid;i<4000;i+=256)  ops[i]=src[i];
    for (int i=tid;i<10000;i+=256) Ws[i]=W2[i];
    if (tid<200) a2s[tid]=a2[tid];
    __syncthreads();
    for (int i=tid;i<4000;i+=256){
        int n=i/100, o=i-n*100;
        float acc=0.f;
        #pragma unroll 4
        for (int k=0;k<100;k++) acc=fmaf(ops[n*100+k], Ws[k*100+o], acc);
        hg[i]=acc;
    }
    __syncthreads();
    for (int t=warp;t<41;t+=8){
        const float* rowp = (t<40)? hg + t*100 : hg;
        const float* av   = (t<40)? a2s        : a2s+100;
        float s=0.f;
        for (int k=lane;k<100;k+=32) s += rowp[k]*av[k];
        #pragma unroll
        for (int o=16;o;o>>=1) s += __shfl_xor_sync(0xffffffffu, s, o);
        if (lane==0) ebuf[t]=s;
    }
    __syncthreads();
    if (tid<40){
        float x = ebuf[tid] + ebuf[40];
        ebuf[tid] = (x>0.f)? x : 0.2f*x;
    }
    __syncthreads();
    if (tid<32){
        float v = ebuf[tid];
        if (tid<8) v = fmaxf(v, ebuf[tid+32]);
        #pragma unroll
        for (int o=16;o;o>>=1) v = fmaxf(v, __shfl_xor_sync(0xffffffffu, v, o));
        if (tid==0) red[0]=v;
    }
    __syncthreads();
    if (tid<40) att[tid]=__expf(ebuf[tid]-red[0]);
    __syncthreads();
    if (tid<32){
        float v = att[tid] + ((tid<8)? att[tid+32] : 0.f);
        #pragma unroll
        for (int o=16;o;o>>=1) v += __shfl_xor_sync(0xffffffffu, v, o);
        if (tid==0) red[1]=1.f/v;
    }
    __syncthreads();
    if (tid<40) att[tid]=fmaxf(att[tid]*red[1]-0.001f, 0.f);
    __syncthreads();
    if (tid<100){
        float acc=0.f;
        #pragma unroll 8
        for (int n=0;n<40;n++) acc += att[n]*hg[n*100+tid];
        output_att[(size_t)b*100+tid]=acc;
    }
    if ((b&1)==0){
        const float* srow = g_op + (size_t)b*40*100;
        float* drow = op2 + (size_t)(b>>1)*100;
        if (tid<100) drow[tid]=srow[tid];
    }
}

// ---------------------------------------------------------------------------
extern "C" void kernel_launch(void* const* d_in, const int* in_sizes, int n_in,
                              void* d_out, int out_size)
{
    const int*   bh    = (const int*)  d_in[0];
    const int*   br    = (const int*)  d_in[1];
    const int*   bt    = (const int*)  d_in[2];
    const float* ent   = (const float*)d_in[3];
    const float* rel   = (const float*)d_in[4];
    const float* ent1  = (const float*)d_in[5];
    const float* rel1  = (const float*)d_in[6];
    const float* Wih_f = (const float*)d_in[7];
    const float* Whh_f = (const float*)d_in[8];
    const float* b_f   = (const float*)d_in[9];
    const float* Wih_b = (const float*)d_in[10];
    const float* Whh_b = (const float*)d_in[11];
    const float* b_b   = (const float*)d_in[12];
    const float* Wih_p = (const float*)d_in[13];
    const float* Whh_p = (const float*)d_in[14];
    const float* b_p   = (const float*)d_in[15];
    const float* W1    = (const float*)d_in[16];
    const float* a1    = (const float*)d_in[17];
    const float* W2    = (const float*)d_in[18];
    const float* a2    = (const float*)d_in[19];

    float* out        = (float*)d_out;
    float* out2       = out;                          // [1024,600]
    float* out_att    = out + 1024*600;               // [2048,600]
    float* op2        = out + 1024*600 + 2048*600;    // [1024,100]
    float* output_att = op2 + 1024*100;               // [2048,100]

    cudaFuncSetAttribute(gat2_kernel, cudaFuncAttributeMaxDynamicSharedMemorySize, GAT2_SMEM);
    cudaFuncSetAttribute(mma_f16,     cudaFuncAttributeMaxDynamicSharedMemorySize, MMF_SMEM);

    convB_kernel<<<(600*600 + 255)/256, 256>>>(W1);
    convW6_kernel<<<(6*400*100 + 255)/256, 256>>>(Whh_f, Whh_b, Whh_p, Wih_f, Wih_b, Wih_p);
    convE_kernel<<<(2*(NENT+NRELS)*100 + 255)/256, 256>>>(ent, ent1, rel, rel1);

    dim3 pe(4, NENT_P/64, 3);
    mma_f16<<<pe, 256, MMF_SMEM>>>(2);
    dim3 pr(4, 4, 3);
    mma_f16<<<pr, 256, MMF_SMEM>>>(3);

    step1_kernel<<<(3*NENT*100 + 255)/256, 256>>>(b_f, b_b, b_p);

    mma_f16<<<pe, 256, MMF_SMEM>>>(4);

    dim3 sg(M_TOTAL/64, 3);
    step12_kernel<<<sg, 256>>>(bh, br, bt, b_f, b_b, b_p);

    dim3 rg(4, M_TOTAL/64, 3);
    mma_f16<<<rg, 256, MMF_SMEM>>>(1);

    step3_kernel<<<sg, 256>>>(bh, bt, b_f, b_b, b_p);

    dim3 gg(5, M_TOTAL/64, 1);
    mma_f16<<<gg, 256, MMF_SMEM>>>(0);

    gat1_att<<<NGROUP, 256>>>(a1, out_att, out2);

    gat2_kernel<<<NGROUP, 256, GAT2_SMEM>>>(W2, a2, output_att, op2);

    (void)in_sizes; (void)n_in; (void)out_size;
}